// round 6
// baseline (speedup 1.0000x reference)
#include <cuda_runtime.h>
#include <cuda_fp16.h>
#include <math.h>
#include <stdint.h>

// ---------------------------------------------------------------------------
// RockTS encoder: BS=64, NP=64, NV=7, PL=16, DM=768, NH=12, DK=64, DF=3072, NL=3
// M = 28672 rows. Outputs: z | h_t | attn concatenated in d_out.
// R6: hgemm BM=128/BN=256 warp-tile 64x64, 3-stage cp.async; fp16 QKV path.
// ---------------------------------------------------------------------------

#define MROWS 28672
#define DM    768
#define DF    3072
#define LSEQ  64
#define BH    448
#define NHEAD 12
#define OUTSZ 22020096

__device__ float  g_u[MROWS * DM];
__device__ __half g_uh[MROWS * DM];
__device__ __half g_qh[MROWS * DM];
__device__ __half g_kh[MROWS * DM];
__device__ __half g_vh[MROWS * DM];
__device__ __half g_oh[MROWS * DM];
__device__ float  g_t[MROWS * DM];
__device__ __half g_ffh[MROWS * DF];
__device__ float  g_scores[BH * NHEAD * LSEQ * LSEQ];
__device__ float  g_stats[2 * DM];
__device__ __half g_wqt[3 * DM * DM];
__device__ __half g_wkt[3 * DM * DM];
__device__ __half g_wvt[3 * DM * DM];
__device__ __half g_wot[3 * DM * DM];
__device__ __half g_w1t[3 * DM * DF];
__device__ __half g_w2t[3 * DF * DM];

// ---------------------------------------------------------------------------
// fp16 MMA GEMM: C[M,N] = A[M,K] @ Bt[N,K]^T + bias (opt GELU)
// BM=128, BN=256, BK=32, 8 warps (2m x 4n), warp tile 64x64, m16n8k16,
// ldmatrix fragments, 3-stage cp.async pipeline (dynamic smem 92160 B).
// ---------------------------------------------------------------------------
#define SROWH   40
#define A_STAGE (128 * SROWH * 2)   // 10240 B
#define B_STAGE (256 * SROWH * 2)   // 20480 B
#define HG_SMEM (3 * (A_STAGE + B_STAGE))  // 92160 B

__device__ __forceinline__ void cpasync16u(uint32_t sa, const void* gp) {
    asm volatile("cp.async.cg.shared.global [%0], [%1], 16;" :: "r"(sa), "l"(gp));
}

template<int GELU_EPI, int WRITE_F, int WRITE_H>
__global__ __launch_bounds__(256) void hgemm(
    const __half* __restrict__ A, const __half* __restrict__ Bt,
    const float* __restrict__ bias, float* __restrict__ Cf,
    __half* __restrict__ Ch, int N, int K)
{
    extern __shared__ char dsm[];
    const uint32_t sb  = (uint32_t)__cvta_generic_to_shared(dsm);
    const uint32_t sbA = sb;
    const uint32_t sbB = sb + 3 * A_STAGE;

    const int tid  = threadIdx.x;
    const int wid  = tid >> 5, lane = tid & 31;
    const int g    = lane >> 2, tig = lane & 3;
    const int wm   = (wid & 1) * 64;
    const int wn   = (wid >> 1) * 64;
    const int m0   = blockIdx.y * 128, n0 = blockIdx.x * 256;
    const int NK   = K >> 5;

    // ldmatrix lane addressing
    const int arow  = lane & 15;
    const int akoff = (lane & 16) >> 1;
    const int nrow  = ((lane & 16) >> 1) + (lane & 7);
    const int bkoff = lane & 8;
    const uint32_t aOff = ((wm + arow) * SROWH + akoff) * 2;
    const uint32_t bOff = ((wn + nrow) * SROWH + bkoff) * 2;

    float acc[32][4];
#pragma unroll
    for (int i = 0; i < 32; i++)
#pragma unroll
        for (int j = 0; j < 4; j++) acc[i][j] = 0.f;

    // load a stage: A 512 chunks, B 1024 chunks (16B each)
    auto load_stage = [&](int stg, int it) {
        const __half* Ab = A + (size_t)m0 * K + it * 32;
        const __half* Bb = Bt + (size_t)n0 * K + it * 32;
        uint32_t dA = sbA + stg * A_STAGE;
        uint32_t dB = sbB + stg * B_STAGE;
#pragma unroll
        for (int r = 0; r < 2; r++) {
            int c = tid + 256 * r;
            int row = c >> 2, cj = c & 3;
            cpasync16u(dA + (row * SROWH + cj * 8) * 2, Ab + (size_t)row * K + cj * 8);
        }
#pragma unroll
        for (int r = 0; r < 4; r++) {
            int c = tid + 256 * r;
            int row = c >> 2, cj = c & 3;
            cpasync16u(dB + (row * SROWH + cj * 8) * 2, Bb + (size_t)row * K + cj * 8);
        }
        asm volatile("cp.async.commit_group;");
    };

    load_stage(0, 0);
    if (NK > 1) load_stage(1, 1);

    for (int it = 0; it < NK; it++) {
        const int s = it % 3;
        if (it + 2 < NK) {
            load_stage((it + 2) % 3, it + 2);
            asm volatile("cp.async.wait_group 2;");
        } else if (it + 1 < NK) {
            asm volatile("cp.async.wait_group 1;");
        } else {
            asm volatile("cp.async.wait_group 0;");
        }
        __syncthreads();

        const uint32_t aS = sbA + s * A_STAGE + aOff;
        const uint32_t bS = sbB + s * B_STAGE + bOff;
#pragma unroll
        for (int ks = 0; ks < 2; ks++) {
            uint32_t a[4][4], b[8][2];
#pragma unroll
            for (int mt = 0; mt < 4; mt++) {
                uint32_t ad = aS + mt * (16 * SROWH * 2) + ks * 32;
                asm volatile("ldmatrix.sync.aligned.m8n8.x4.shared.b16 {%0,%1,%2,%3}, [%4];"
                             : "=r"(a[mt][0]), "=r"(a[mt][1]), "=r"(a[mt][2]), "=r"(a[mt][3])
                             : "r"(ad));
            }
#pragma unroll
            for (int p = 0; p < 4; p++) {
                uint32_t bd = bS + p * (16 * SROWH * 2) + ks * 32;
                asm volatile("ldmatrix.sync.aligned.m8n8.x4.shared.b16 {%0,%1,%2,%3}, [%4];"
                             : "=r"(b[2 * p][0]), "=r"(b[2 * p][1]),
                               "=r"(b[2 * p + 1][0]), "=r"(b[2 * p + 1][1])
                             : "r"(bd));
            }
#pragma unroll
            for (int mt = 0; mt < 4; mt++)
#pragma unroll
                for (int nt = 0; nt < 8; nt++) {
                    float* c = acc[mt * 8 + nt];
                    asm volatile(
                        "mma.sync.aligned.m16n8k16.row.col.f32.f16.f16.f32 "
                        "{%0,%1,%2,%3}, {%4,%5,%6,%7}, {%8,%9}, {%0,%1,%2,%3};"
                        : "+f"(c[0]), "+f"(c[1]), "+f"(c[2]), "+f"(c[3])
                        : "r"(a[mt][0]), "r"(a[mt][1]), "r"(a[mt][2]), "r"(a[mt][3]),
                          "r"(b[nt][0]), "r"(b[nt][1]));
                }
        }
        __syncthreads();
    }

    // epilogue
#pragma unroll
    for (int mt = 0; mt < 4; mt++) {
#pragma unroll
        for (int nt = 0; nt < 8; nt++) {
            const float* c = acc[mt * 8 + nt];
            int col = n0 + wn + nt * 8 + 2 * tig;
            float b0 = bias[col], b1 = bias[col + 1];
            int r0 = m0 + wm + mt * 16 + g;
            float2 v0, v1;
            v0.x = c[0] + b0; v0.y = c[1] + b1;
            v1.x = c[2] + b0; v1.y = c[3] + b1;
            if (GELU_EPI) {
                v0.x = 0.5f * v0.x * (1.0f + erff(v0.x * 0.70710678118654752f));
                v0.y = 0.5f * v0.y * (1.0f + erff(v0.y * 0.70710678118654752f));
                v1.x = 0.5f * v1.x * (1.0f + erff(v1.x * 0.70710678118654752f));
                v1.y = 0.5f * v1.y * (1.0f + erff(v1.y * 0.70710678118654752f));
            }
            if (WRITE_F) {
                *(float2*)&Cf[(size_t)r0 * N + col] = v0;
                *(float2*)&Cf[(size_t)(r0 + 8) * N + col] = v1;
            }
            if (WRITE_H) {
                __half2 h0, h1;
                h0.x = __float2half(v0.x); h0.y = __float2half(v0.y);
                h1.x = __float2half(v1.x); h1.y = __float2half(v1.y);
                *(__half2*)&Ch[(size_t)r0 * N + col] = h0;
                *(__half2*)&Ch[(size_t)(r0 + 8) * N + col] = h1;
            }
        }
    }
}

// ---------------------------------------------------------------------------
// fp32 SGEMM (patch embed, K=16)
// ---------------------------------------------------------------------------
__global__ __launch_bounds__(256, 2) void gemm_kernel(
    const float* __restrict__ A, const float* __restrict__ B,
    const float* __restrict__ bias, float* __restrict__ C,
    int Mdim, int Ndim, int Kdim)
{
    __shared__ float As[16][128];
    __shared__ float Bs[16][132];
    const int tid = threadIdx.x;
    const int tx = tid & 15, ty = tid >> 4;
    const int m0 = blockIdx.y * 128, n0 = blockIdx.x * 128;
    float acc[8][8];
#pragma unroll
    for (int i = 0; i < 8; i++)
#pragma unroll
        for (int j = 0; j < 8; j++) acc[i][j] = 0.f;
    for (int k0 = 0; k0 < Kdim; k0 += 16) {
#pragma unroll
        for (int s = 0; s < 2; s++) {
            int f4 = tid + 256 * s;
            int row = f4 >> 2, kq = (f4 & 3) * 4;
            float4 av = *(const float4*)&A[(size_t)(m0 + row) * Kdim + k0 + kq];
            As[kq + 0][row] = av.x; As[kq + 1][row] = av.y;
            As[kq + 2][row] = av.z; As[kq + 3][row] = av.w;
        }
#pragma unroll
        for (int s = 0; s < 2; s++) {
            int f4 = tid + 256 * s;
            int row = f4 >> 5, nq = (f4 & 31) * 4;
            *(float4*)&Bs[row][nq] = *(const float4*)&B[(size_t)(k0 + row) * Ndim + n0 + nq];
        }
        __syncthreads();
#pragma unroll
        for (int k = 0; k < 16; k++) {
            float a[8], b[8];
            *(float4*)&a[0] = *(const float4*)&As[k][ty * 8];
            *(float4*)&a[4] = *(const float4*)&As[k][ty * 8 + 4];
            *(float4*)&b[0] = *(const float4*)&Bs[k][tx * 8];
            *(float4*)&b[4] = *(const float4*)&Bs[k][tx * 8 + 4];
#pragma unroll
            for (int i = 0; i < 8; i++)
#pragma unroll
                for (int j = 0; j < 8; j++) acc[i][j] += a[i] * b[j];
        }
        __syncthreads();
    }
#pragma unroll
    for (int i = 0; i < 8; i++) {
        int row = m0 + ty * 8 + i;
#pragma unroll
        for (int j = 0; j < 8; j++) {
            int col = n0 + tx * 8 + j;
            C[(size_t)row * Ndim + col] = acc[i][j] + bias[col];
        }
    }
}

// ---------------------------------------------------------------------------
// Weight transpose + fp16 convert: out[N,K] = half(in[K,N]^T)
// ---------------------------------------------------------------------------
__global__ void wtrans_kernel(const float* __restrict__ in, __half* __restrict__ out,
                              int R, int Ccols)
{
    __shared__ float tl[32][33];
    int c0 = blockIdx.x * 32, r0 = blockIdx.y * 32;
#pragma unroll
    for (int i = 0; i < 32; i += 8)
        tl[threadIdx.y + i][threadIdx.x] = in[(size_t)(r0 + threadIdx.y + i) * Ccols + c0 + threadIdx.x];
    __syncthreads();
#pragma unroll
    for (int i = 0; i < 32; i += 8)
        out[(size_t)(c0 + threadIdx.y + i) * R + r0 + threadIdx.x] =
            __float2half(tl[threadIdx.x][threadIdx.y + i]);
}

// ---------------------------------------------------------------------------
// Fused attention per (batch, head), register-blocked 4x4 per thread.
// Inputs fp16, math fp32. smem: Qs|Ks|Ss 64*65 each = 49920 B
// ---------------------------------------------------------------------------
__global__ __launch_bounds__(256) void attn_kernel(
    const __half* __restrict__ Q, const __half* __restrict__ K,
    const __half* __restrict__ V, float* __restrict__ scores,
    __half* __restrict__ O, float* __restrict__ attn_out, int has_prev)
{
    extern __shared__ float sm[];
    float* Qs = sm;
    float* Ks = sm + 4160;
    float* Ss = sm + 8320;

    const int bh = blockIdx.x;
    const int bv = bh / NHEAD, h = bh % NHEAD;
    const int row0 = bv * LSEQ, c0 = h * 64;
    const int t = threadIdx.x;
    const size_t sb = (size_t)bh * 4096;

#pragma unroll
    for (int s = 0; s < 16; s++) {
        int e = t + 256 * s;
        int i = e >> 6, kk = e & 63;
        Qs[i * 65 + kk] = __half2float(Q[(size_t)(row0 + i) * DM + c0 + kk]);
        Ks[i * 65 + kk] = __half2float(K[(size_t)(row0 + i) * DM + c0 + kk]);
    }
    __syncthreads();

    const int i0 = (t >> 4) * 4;
    const int jc = t & 15;
    float acc[4][4];
#pragma unroll
    for (int a = 0; a < 4; a++)
#pragma unroll
        for (int b = 0; b < 4; b++) acc[a][b] = 0.f;

    for (int kk = 0; kk < 64; kk++) {
        float qa[4], kb[4];
#pragma unroll
        for (int a = 0; a < 4; a++) qa[a] = Qs[(i0 + a) * 65 + kk];
#pragma unroll
        for (int b = 0; b < 4; b++) kb[b] = Ks[(jc + 16 * b) * 65 + kk];
#pragma unroll
        for (int a = 0; a < 4; a++)
#pragma unroll
            for (int b = 0; b < 4; b++) acc[a][b] += qa[a] * kb[b];
    }

#pragma unroll
    for (int a = 0; a < 4; a++) {
#pragma unroll
        for (int b = 0; b < 4; b++) {
            int i = i0 + a, j = jc + 16 * b;
            float val = acc[a][b] * 0.125f;
            if (has_prev) val += scores[sb + i * 64 + j];
            scores[sb + i * 64 + j] = val;
            Ss[i * 65 + j] = val;
        }
    }
    __syncthreads();

    const int w = t >> 5, lane = t & 31;
#pragma unroll
    for (int p = 0; p < 8; p++) {
        int r = w * 8 + p;
        float v0 = Ss[r * 65 + lane], v1 = Ss[r * 65 + lane + 32];
        float mx = fmaxf(v0, v1);
#pragma unroll
        for (int off = 16; off > 0; off >>= 1)
            mx = fmaxf(mx, __shfl_xor_sync(0xffffffffu, mx, off));
        float e0 = __expf(v0 - mx), e1 = __expf(v1 - mx);
        float sumv = e0 + e1;
#pragma unroll
        for (int off = 16; off > 0; off >>= 1)
            sumv += __shfl_xor_sync(0xffffffffu, sumv, off);
        float inv = 1.0f / sumv;
        e0 *= inv; e1 *= inv;
        Ss[r * 65 + lane] = e0;
        Ss[r * 65 + lane + 32] = e1;
        if (attn_out) {
            attn_out[sb + r * 64 + lane] = e0;
            attn_out[sb + r * 64 + lane + 32] = e1;
        }
    }
    __syncthreads();

#pragma unroll
    for (int s = 0; s < 16; s++) {
        int e = t + 256 * s;
        int i = e >> 6, kk = e & 63;
        Ks[i * 65 + kk] = __half2float(V[(size_t)(row0 + i) * DM + c0 + kk]);
    }
    __syncthreads();

    float acc2[4][4];
#pragma unroll
    for (int a = 0; a < 4; a++)
#pragma unroll
        for (int b = 0; b < 4; b++) acc2[a][b] = 0.f;

    for (int j = 0; j < 64; j++) {
        float sa[4], vb[4];
#pragma unroll
        for (int a = 0; a < 4; a++) sa[a] = Ss[(i0 + a) * 65 + j];
#pragma unroll
        for (int b = 0; b < 4; b++) vb[b] = Ks[j * 65 + jc + 16 * b];
#pragma unroll
        for (int a = 0; a < 4; a++)
#pragma unroll
            for (int b = 0; b < 4; b++) acc2[a][b] += sa[a] * vb[b];
    }

#pragma unroll
    for (int a = 0; a < 4; a++)
#pragma unroll
        for (int b = 0; b < 4; b++)
            O[(size_t)(row0 + i0 + a) * DM + c0 + jc + 16 * b] = __float2half(acc2[a][b]);
}

// ---------------------------------------------------------------------------
// BatchNorm
// ---------------------------------------------------------------------------
__global__ void zero_stats_kernel(float* stats)
{
    int idx = blockIdx.x * 256 + threadIdx.x;
    if (idx < 2 * DM) stats[idx] = 0.f;
}

__global__ __launch_bounds__(256) void bn_add_stats_kernel(
    float* __restrict__ u, const float* __restrict__ t2, float* __restrict__ stats)
{
    const int c0 = threadIdx.x;
    float s0 = 0, s1 = 0, s2 = 0, q0 = 0, q1 = 0, q2 = 0;
    const int rbase = blockIdx.x * 128;
    for (int r = 0; r < 128; r++) {
        size_t base = (size_t)(rbase + r) * DM;
        float a0 = u[base + c0] + t2[base + c0];
        float a1 = u[base + c0 + 256] + t2[base + c0 + 256];
        float a2 = u[base + c0 + 512] + t2[base + c0 + 512];
        u[base + c0] = a0; u[base + c0 + 256] = a1; u[base + c0 + 512] = a2;
        s0 += a0; s1 += a1; s2 += a2;
        q0 += a0 * a0; q1 += a1 * a1; q2 += a2 * a2;
    }
    atomicAdd(&stats[c0], s0);
    atomicAdd(&stats[c0 + 256], s1);
    atomicAdd(&stats[c0 + 512], s2);
    atomicAdd(&stats[DM + c0], q0);
    atomicAdd(&stats[DM + c0 + 256], q1);
    atomicAdd(&stats[DM + c0 + 512], q2);
}

__global__ __launch_bounds__(256) void bn_norm_kernel(
    float* __restrict__ u, __half* __restrict__ uh, const float* __restrict__ stats,
    const float* __restrict__ g, const float* __restrict__ be)
{
    int idx = blockIdx.x * 256 + threadIdx.x;
    int c = idx % DM;
    const float invM = 1.0f / (float)MROWS;
    float mean = stats[c] * invM;
    float var = stats[DM + c] * invM - mean * mean;
    float iv = rsqrtf(var + 1e-5f);
    float val = (u[idx] - mean) * iv * g[c] + be[c];
    u[idx] = val;
    uh[idx] = __float2half(val);
}

// ---------------------------------------------------------------------------
// Misc remap / transposes
// ---------------------------------------------------------------------------
__global__ __launch_bounds__(256) void remap_embed_kernel(
    const float* __restrict__ h, const float* __restrict__ Wpos,
    float* __restrict__ u, __half* __restrict__ uh)
{
    int idx = blockIdx.x * 256 + threadIdx.x;
    int ru = idx / DM, d = idx % DM;
    int bv = ru >> 6, n = ru & 63;
    int b = bv / 7, v = bv % 7;
    int rh = (b * 64 + n) * 7 + v;
    float val = h[(size_t)rh * DM + d] + Wpos[n * DM + d];
    u[idx] = val;
    uh[idx] = __float2half(val);
}

__global__ void transpose_h_kernel(const float* __restrict__ h, float* __restrict__ out)
{
    __shared__ float tile[32][33];
    int bv = blockIdx.z, b = bv / 7, v = bv % 7;
    int d0 = blockIdx.x * 32, n0 = blockIdx.y * 32;
#pragma unroll
    for (int i = 0; i < 32; i += 8) {
        int n = n0 + threadIdx.y + i;
        int d = d0 + threadIdx.x;
        tile[threadIdx.y + i][threadIdx.x] = h[((size_t)(b * 64 + n) * 7 + v) * DM + d];
    }
    __syncthreads();
#pragma unroll
    for (int i = 0; i < 32; i += 8) {
        int d = d0 + threadIdx.y + i;
        int n = n0 + threadIdx.x;
        out[((size_t)bv * DM + d) * LSEQ + n] = tile[threadIdx.x][threadIdx.y + i];
    }
}

__global__ void transpose_z_kernel(const float* __restrict__ u, float* __restrict__ out)
{
    __shared__ float tile[32][33];
    int bv = blockIdx.z;
    int d0 = blockIdx.x * 32, n0 = blockIdx.y * 32;
#pragma unroll
    for (int i = 0; i < 32; i += 8) {
        int n = n0 + threadIdx.y + i;
        int d = d0 + threadIdx.x;
        tile[threadIdx.y + i][threadIdx.x] = u[(size_t)(bv * 64 + n) * DM + d];
    }
    __syncthreads();
#pragma unroll
    for (int i = 0; i < 32; i += 8) {
        int d = d0 + threadIdx.y + i;
        int n = n0 + threadIdx.x;
        out[((size_t)bv * DM + d) * LSEQ + n] = tile[threadIdx.x][threadIdx.y + i];
    }
}

// ---------------------------------------------------------------------------

extern "C" void kernel_launch(void* const* d_in, const int* in_sizes, int n_in,
                              void* d_out, int out_size)
{
    const float* x    = (const float*)d_in[0];
    const float* Wp   = (const float*)d_in[1];
    const float* bp   = (const float*)d_in[2];
    const float* Wpos = (const float*)d_in[3];
    const float* Wq   = (const float*)d_in[4];
    const float* bq   = (const float*)d_in[5];
    const float* Wk   = (const float*)d_in[6];
    const float* bk   = (const float*)d_in[7];
    const float* Wv   = (const float*)d_in[8];
    const float* bv_  = (const float*)d_in[9];
    const float* Wo   = (const float*)d_in[10];
    const float* bo   = (const float*)d_in[11];
    const float* g1   = (const float*)d_in[12];
    const float* be1  = (const float*)d_in[13];
    const float* W1   = (const float*)d_in[14];
    const float* b1   = (const float*)d_in[15];
    const float* W2   = (const float*)d_in[16];
    const float* b2   = (const float*)d_in[17];
    const float* g2   = (const float*)d_in[18];
    const float* be2  = (const float*)d_in[19];

    float* out      = (float*)d_out;
    float* out_z    = out;
    float* out_h    = out + OUTSZ;
    float* out_attn = out + 2 * (size_t)OUTSZ;

    float *u, *t, *sc, *st;
    __half *uh, *qh, *kh, *vh, *oh, *ffh, *wqt, *wkt, *wvt, *wot, *w1t, *w2t;
    cudaGetSymbolAddress((void**)&u,  g_u);
    cudaGetSymbolAddress((void**)&uh, g_uh);
    cudaGetSymbolAddress((void**)&qh, g_qh);
    cudaGetSymbolAddress((void**)&kh, g_kh);
    cudaGetSymbolAddress((void**)&vh, g_vh);
    cudaGetSymbolAddress((void**)&oh, g_oh);
    cudaGetSymbolAddress((void**)&t,  g_t);
    cudaGetSymbolAddress((void**)&ffh, g_ffh);
    cudaGetSymbolAddress((void**)&sc, g_scores);
    cudaGetSymbolAddress((void**)&st, g_stats);
    cudaGetSymbolAddress((void**)&wqt, g_wqt);
    cudaGetSymbolAddress((void**)&wkt, g_wkt);
    cudaGetSymbolAddress((void**)&wvt, g_wvt);
    cudaGetSymbolAddress((void**)&wot, g_wot);
    cudaGetSymbolAddress((void**)&w1t, g_w1t);
    cudaGetSymbolAddress((void**)&w2t, g_w2t);

    cudaFuncSetAttribute(attn_kernel, cudaFuncAttributeMaxDynamicSharedMemorySize, 49920);
    cudaFuncSetAttribute(hgemm<0, 0, 1>, cudaFuncAttributeMaxDynamicSharedMemorySize, HG_SMEM);
    cudaFuncSetAttribute(hgemm<0, 1, 0>, cudaFuncAttributeMaxDynamicSharedMemorySize, HG_SMEM);
    cudaFuncSetAttribute(hgemm<1, 0, 1>, cudaFuncAttributeMaxDynamicSharedMemorySize, HG_SMEM);

    const dim3 blk(256);
    const int elemBlocks = (MROWS * DM) / 256;
    const dim3 tgrid(24, 2, BH);
    const dim3 tblk32(32, 8);
    const dim3 gD(DM / 256, MROWS / 128);   // (3, 224)
    const dim3 gF(DF / 256, MROWS / 128);   // (12, 224)
    const dim3 gdd(DM / 32, DM / 32);
    const dim3 g1d(DF / 32, DM / 32);
    const dim3 g2d(DM / 32, DF / 32);

    // Keep launch order so an early hgemm gets profiled.
    wtrans_kernel<<<gdd, tblk32>>>(Wq, wqt, DM, DM);                               // 0
    gemm_kernel<<<dim3(DM / 128, MROWS / 128), blk>>>(x, Wp, bp, t, MROWS, DM, 16);// 1
    remap_embed_kernel<<<elemBlocks, blk>>>(t, Wpos, u, uh);                       // 2
    transpose_h_kernel<<<tgrid, tblk32>>>(t, out_h);                               // 3
    wtrans_kernel<<<gdd, tblk32>>>(Wk, wkt, DM, DM);                               // 4
    hgemm<0, 0, 1><<<gD, blk, HG_SMEM>>>(uh, wqt, bq, nullptr, qh, DM, DM);        // 5

    wtrans_kernel<<<gdd, tblk32>>>(Wv, wvt, DM, DM);
    wtrans_kernel<<<gdd, tblk32>>>(Wo, wot, DM, DM);
    wtrans_kernel<<<g1d, tblk32>>>(W1, w1t, DM, DF);
    wtrans_kernel<<<g2d, tblk32>>>(W2, w2t, DF, DM);
    for (int l = 1; l < 3; l++) {
        wtrans_kernel<<<gdd, tblk32>>>(Wq + (size_t)l * DM * DM, wqt + (size_t)l * DM * DM, DM, DM);
        wtrans_kernel<<<gdd, tblk32>>>(Wk + (size_t)l * DM * DM, wkt + (size_t)l * DM * DM, DM, DM);
        wtrans_kernel<<<gdd, tblk32>>>(Wv + (size_t)l * DM * DM, wvt + (size_t)l * DM * DM, DM, DM);
        wtrans_kernel<<<gdd, tblk32>>>(Wo + (size_t)l * DM * DM, wot + (size_t)l * DM * DM, DM, DM);
        wtrans_kernel<<<g1d, tblk32>>>(W1 + (size_t)l * DM * DF, w1t + (size_t)l * DM * DF, DM, DF);
        wtrans_kernel<<<g2d, tblk32>>>(W2 + (size_t)l * DF * DM, w2t + (size_t)l * DF * DM, DF, DM);
    }

    for (int l = 0; l < 3; l++) {
        if (l > 0)
            hgemm<0, 0, 1><<<gD, blk, HG_SMEM>>>(uh, wqt + (size_t)l * DM * DM, bq + l * DM, nullptr, qh, DM, DM);
        hgemm<0, 0, 1><<<gD, blk, HG_SMEM>>>(uh, wkt + (size_t)l * DM * DM, bk + l * DM, nullptr, kh, DM, DM);
        hgemm<0, 0, 1><<<gD, blk, HG_SMEM>>>(uh, wvt + (size_t)l * DM * DM, bv_ + l * DM, nullptr, vh, DM, DM);

        attn_kernel<<<BH * NHEAD, 256, 49920>>>(
            qh, kh, vh, sc, oh, (l == 2) ? out_attn : nullptr, (l > 0) ? 1 : 0);

        hgemm<0, 1, 0><<<gD, blk, HG_SMEM>>>(oh, wot + (size_t)l * DM * DM, bo + l * DM, t, nullptr, DM, DM);

        zero_stats_kernel<<<6, 256>>>(st);
        bn_add_stats_kernel<<<MROWS / 128, 256>>>(u, t, st);
        bn_norm_kernel<<<elemBlocks, blk>>>(u, uh, st, g1 + l * DM, be1 + l * DM);

        hgemm<1, 0, 1><<<gF, blk, HG_SMEM>>>(uh, w1t + (size_t)l * DM * DF, b1 + l * DF, nullptr, ffh, DF, DM);
        hgemm<0, 1, 0><<<gD, blk, HG_SMEM>>>(ffh, w2t + (size_t)l * DF * DM, b2 + l * DM, t, nullptr, DM, DF);

        zero_stats_kernel<<<6, 256>>>(st);
        bn_add_stats_kernel<<<MROWS / 128, 256>>>(u, t, st);
        bn_norm_kernel<<<elemBlocks, blk>>>(u, uh, st, g2 + l * DM, be2 + l * DM);
    }

    transpose_z_kernel<<<tgrid, tblk32>>>(u, out_z);
}

// round 7
// speedup vs baseline: 1.1663x; 1.1663x over previous
#include <cuda_runtime.h>
#include <cuda_fp16.h>
#include <math.h>
#include <stdint.h>

// ---------------------------------------------------------------------------
// RockTS encoder: BS=64, NP=64, NV=7, PL=16, DM=768, NH=12, DK=64, DF=3072, NL=3
// M = 28672 rows. Outputs: z | h_t | attn concatenated in d_out.
// R7: R5-shape hgemm (128x128, 2-stage, 2 CTA/SM) + BN stats fused in epilogue.
// ---------------------------------------------------------------------------

#define MROWS 28672
#define DM    768
#define DF    3072
#define LSEQ  64
#define BH    448
#define NHEAD 12
#define OUTSZ 22020096

__device__ float  g_u[MROWS * DM];
__device__ __half g_uh[MROWS * DM];
__device__ __half g_qh[MROWS * DM];
__device__ __half g_kh[MROWS * DM];
__device__ __half g_vh[MROWS * DM];
__device__ __half g_oh[MROWS * DM];
__device__ float  g_t[MROWS * DM];
__device__ __half g_ffh[MROWS * DF];
__device__ float  g_scores[BH * NHEAD * LSEQ * LSEQ];
__device__ float  g_stats[2 * DM];
__device__ __half g_wqt[3 * DM * DM];
__device__ __half g_wkt[3 * DM * DM];
__device__ __half g_wvt[3 * DM * DM];
__device__ __half g_wot[3 * DM * DM];
__device__ __half g_w1t[3 * DM * DF];
__device__ __half g_w2t[3 * DF * DM];

// ---------------------------------------------------------------------------
// fp16 MMA GEMM (R5 shape): C[M,N] = A[M,K] @ Bt[N,K]^T + bias
// BM=BN=128, BK=32, 8 warps (2m x 4n), warp tile 64x32, m16n8k16, ldmatrix,
// 2-stage cp.async. RESID mode: C += U (residual), write U, atomic BN stats.
// ---------------------------------------------------------------------------
#define SROWH 40
#define STAGE_BYTES (128 * SROWH * 2)

__device__ __forceinline__ void cpasync16(void* smp, const void* gp) {
    uint32_t sa = (uint32_t)__cvta_generic_to_shared(smp);
    asm volatile("cp.async.cg.shared.global [%0], [%1], 16;" :: "r"(sa), "l"(gp));
}

template<int GELU_EPI, int WRITE_F, int WRITE_H, int RESID>
__global__ __launch_bounds__(256, 2) void hgemm(
    const __half* __restrict__ A, const __half* __restrict__ Bt,
    const float* __restrict__ bias, float* __restrict__ Cf,
    __half* __restrict__ Ch, float* __restrict__ U, float* __restrict__ stats,
    int N, int K)
{
    __shared__ __half smA[2][128 * SROWH];
    __shared__ __half smB[2][128 * SROWH];

    const int tid  = threadIdx.x;
    const int wid  = tid >> 5, lane = tid & 31;
    const int g    = lane >> 2, tig = lane & 3;
    const int wm   = (wid & 1) * 64;
    const int wn   = (wid >> 1) * 32;
    const int m0   = blockIdx.y * 128, n0 = blockIdx.x * 128;
    const int NK   = K >> 5;

    const int arow  = lane & 15;
    const int akoff = (lane & 16) >> 1;
    const int nrow  = ((lane & 16) >> 1) + (lane & 7);
    const int bkoff = lane & 8;
    const uint32_t aBase = (uint32_t)__cvta_generic_to_shared(smA)
                         + ((wm + arow) * SROWH + akoff) * 2;
    const uint32_t bBase = (uint32_t)__cvta_generic_to_shared(smB)
                         + ((wn + nrow) * SROWH + bkoff) * 2;

    float acc[16][4];
#pragma unroll
    for (int i = 0; i < 16; i++)
#pragma unroll
        for (int j = 0; j < 4; j++) acc[i][j] = 0.f;

    {
        const __half* Ab = A + (size_t)m0 * K;
        const __half* Bb = Bt + (size_t)n0 * K;
#pragma unroll
        for (int r = 0; r < 2; r++) {
            int c = tid + 256 * r;
            int row = c >> 2, cj = c & 3;
            cpasync16(&smA[0][row * SROWH + cj * 8], Ab + (size_t)row * K + cj * 8);
            cpasync16(&smB[0][row * SROWH + cj * 8], Bb + (size_t)row * K + cj * 8);
        }
        asm volatile("cp.async.commit_group;");
    }

    for (int it = 0; it < NK; it++) {
        const int s = it & 1;
        if (it + 1 < NK) {
            const __half* Ab = A + (size_t)m0 * K + (it + 1) * 32;
            const __half* Bb = Bt + (size_t)n0 * K + (it + 1) * 32;
#pragma unroll
            for (int r = 0; r < 2; r++) {
                int c = tid + 256 * r;
                int row = c >> 2, cj = c & 3;
                cpasync16(&smA[s ^ 1][row * SROWH + cj * 8], Ab + (size_t)row * K + cj * 8);
                cpasync16(&smB[s ^ 1][row * SROWH + cj * 8], Bb + (size_t)row * K + cj * 8);
            }
            asm volatile("cp.async.commit_group;");
            asm volatile("cp.async.wait_group 1;");
        } else {
            asm volatile("cp.async.wait_group 0;");
        }
        __syncthreads();

        const uint32_t aS = aBase + s * STAGE_BYTES;
        const uint32_t bS = bBase + s * STAGE_BYTES;
#pragma unroll
        for (int ks = 0; ks < 2; ks++) {
            uint32_t a[4][4], b[4][2];
#pragma unroll
            for (int mt = 0; mt < 4; mt++) {
                uint32_t ad = aS + mt * (16 * SROWH * 2) + ks * 32;
                asm volatile("ldmatrix.sync.aligned.m8n8.x4.shared.b16 {%0,%1,%2,%3}, [%4];"
                             : "=r"(a[mt][0]), "=r"(a[mt][1]), "=r"(a[mt][2]), "=r"(a[mt][3])
                             : "r"(ad));
            }
#pragma unroll
            for (int p = 0; p < 2; p++) {
                uint32_t bd = bS + p * (16 * SROWH * 2) + ks * 32;
                asm volatile("ldmatrix.sync.aligned.m8n8.x4.shared.b16 {%0,%1,%2,%3}, [%4];"
                             : "=r"(b[2 * p][0]), "=r"(b[2 * p][1]),
                               "=r"(b[2 * p + 1][0]), "=r"(b[2 * p + 1][1])
                             : "r"(bd));
            }
#pragma unroll
            for (int mt = 0; mt < 4; mt++)
#pragma unroll
                for (int nt = 0; nt < 4; nt++) {
                    float* c = acc[mt * 4 + nt];
                    asm volatile(
                        "mma.sync.aligned.m16n8k16.row.col.f32.f16.f16.f32 "
                        "{%0,%1,%2,%3}, {%4,%5,%6,%7}, {%8,%9}, {%0,%1,%2,%3};"
                        : "+f"(c[0]), "+f"(c[1]), "+f"(c[2]), "+f"(c[3])
                        : "r"(a[mt][0]), "r"(a[mt][1]), "r"(a[mt][2]), "r"(a[mt][3]),
                          "r"(b[nt][0]), "r"(b[nt][1]));
                }
        }
        __syncthreads();
    }

    // epilogue
    float cs[8], cq[8];
    if (RESID) {
#pragma unroll
        for (int i = 0; i < 8; i++) { cs[i] = 0.f; cq[i] = 0.f; }
    }
#pragma unroll
    for (int mt = 0; mt < 4; mt++) {
#pragma unroll
        for (int nt = 0; nt < 4; nt++) {
            const float* c = acc[mt * 4 + nt];
            int col = n0 + wn + nt * 8 + 2 * tig;
            float b0 = bias[col], b1 = bias[col + 1];
            int r0 = m0 + wm + mt * 16 + g;
            float2 v0, v1;
            v0.x = c[0] + b0; v0.y = c[1] + b1;
            v1.x = c[2] + b0; v1.y = c[3] + b1;
            if (GELU_EPI) {
                v0.x = 0.5f * v0.x * (1.0f + erff(v0.x * 0.70710678118654752f));
                v0.y = 0.5f * v0.y * (1.0f + erff(v0.y * 0.70710678118654752f));
                v1.x = 0.5f * v1.x * (1.0f + erff(v1.x * 0.70710678118654752f));
                v1.y = 0.5f * v1.y * (1.0f + erff(v1.y * 0.70710678118654752f));
            }
            if (RESID) {
                float2 u0 = *(float2*)&U[(size_t)r0 * N + col];
                float2 u1 = *(float2*)&U[(size_t)(r0 + 8) * N + col];
                v0.x += u0.x; v0.y += u0.y;
                v1.x += u1.x; v1.y += u1.y;
                *(float2*)&U[(size_t)r0 * N + col] = v0;
                *(float2*)&U[(size_t)(r0 + 8) * N + col] = v1;
                cs[nt * 2 + 0] += v0.x + v1.x;
                cs[nt * 2 + 1] += v0.y + v1.y;
                cq[nt * 2 + 0] += v0.x * v0.x + v1.x * v1.x;
                cq[nt * 2 + 1] += v0.y * v0.y + v1.y * v1.y;
            }
            if (WRITE_F) {
                *(float2*)&Cf[(size_t)r0 * N + col] = v0;
                *(float2*)&Cf[(size_t)(r0 + 8) * N + col] = v1;
            }
            if (WRITE_H) {
                __half2 h0, h1;
                h0.x = __float2half(v0.x); h0.y = __float2half(v0.y);
                h1.x = __float2half(v1.x); h1.y = __float2half(v1.y);
                *(__half2*)&Ch[(size_t)r0 * N + col] = h0;
                *(__half2*)&Ch[(size_t)(r0 + 8) * N + col] = h1;
            }
        }
    }
    if (RESID) {
        // reduce over the 8 g-lanes (same tig => same columns)
#pragma unroll
        for (int i = 0; i < 8; i++) {
            cs[i] += __shfl_down_sync(0xffffffffu, cs[i], 16);
            cs[i] += __shfl_down_sync(0xffffffffu, cs[i], 8);
            cs[i] += __shfl_down_sync(0xffffffffu, cs[i], 4);
            cq[i] += __shfl_down_sync(0xffffffffu, cq[i], 16);
            cq[i] += __shfl_down_sync(0xffffffffu, cq[i], 8);
            cq[i] += __shfl_down_sync(0xffffffffu, cq[i], 4);
        }
        if (lane < 4) {
#pragma unroll
            for (int nt = 0; nt < 4; nt++) {
                int col = n0 + wn + nt * 8 + 2 * tig;
                atomicAdd(&stats[col],     cs[nt * 2 + 0]);
                atomicAdd(&stats[col + 1], cs[nt * 2 + 1]);
                atomicAdd(&stats[DM + col],     cq[nt * 2 + 0]);
                atomicAdd(&stats[DM + col + 1], cq[nt * 2 + 1]);
            }
        }
    }
}

// ---------------------------------------------------------------------------
// fp32 SGEMM (patch embed, K=16)
// ---------------------------------------------------------------------------
__global__ __launch_bounds__(256, 2) void gemm_kernel(
    const float* __restrict__ A, const float* __restrict__ B,
    const float* __restrict__ bias, float* __restrict__ C,
    int Mdim, int Ndim, int Kdim)
{
    __shared__ float As[16][128];
    __shared__ float Bs[16][132];
    const int tid = threadIdx.x;
    const int tx = tid & 15, ty = tid >> 4;
    const int m0 = blockIdx.y * 128, n0 = blockIdx.x * 128;
    float acc[8][8];
#pragma unroll
    for (int i = 0; i < 8; i++)
#pragma unroll
        for (int j = 0; j < 8; j++) acc[i][j] = 0.f;
    for (int k0 = 0; k0 < Kdim; k0 += 16) {
#pragma unroll
        for (int s = 0; s < 2; s++) {
            int f4 = tid + 256 * s;
            int row = f4 >> 2, kq = (f4 & 3) * 4;
            float4 av = *(const float4*)&A[(size_t)(m0 + row) * Kdim + k0 + kq];
            As[kq + 0][row] = av.x; As[kq + 1][row] = av.y;
            As[kq + 2][row] = av.z; As[kq + 3][row] = av.w;
        }
#pragma unroll
        for (int s = 0; s < 2; s++) {
            int f4 = tid + 256 * s;
            int row = f4 >> 5, nq = (f4 & 31) * 4;
            *(float4*)&Bs[row][nq] = *(const float4*)&B[(size_t)(k0 + row) * Ndim + n0 + nq];
        }
        __syncthreads();
#pragma unroll
        for (int k = 0; k < 16; k++) {
            float a[8], b[8];
            *(float4*)&a[0] = *(const float4*)&As[k][ty * 8];
            *(float4*)&a[4] = *(const float4*)&As[k][ty * 8 + 4];
            *(float4*)&b[0] = *(const float4*)&Bs[k][tx * 8];
            *(float4*)&b[4] = *(const float4*)&Bs[k][tx * 8 + 4];
#pragma unroll
            for (int i = 0; i < 8; i++)
#pragma unroll
                for (int j = 0; j < 8; j++) acc[i][j] += a[i] * b[j];
        }
        __syncthreads();
    }
#pragma unroll
    for (int i = 0; i < 8; i++) {
        int row = m0 + ty * 8 + i;
#pragma unroll
        for (int j = 0; j < 8; j++) {
            int col = n0 + tx * 8 + j;
            C[(size_t)row * Ndim + col] = acc[i][j] + bias[col];
        }
    }
}

// ---------------------------------------------------------------------------
// Weight transpose + fp16 convert: out[N,K] = half(in[K,N]^T)
// ---------------------------------------------------------------------------
__global__ void wtrans_kernel(const float* __restrict__ in, __half* __restrict__ out,
                              int R, int Ccols)
{
    __shared__ float tl[32][33];
    int c0 = blockIdx.x * 32, r0 = blockIdx.y * 32;
#pragma unroll
    for (int i = 0; i < 32; i += 8)
        tl[threadIdx.y + i][threadIdx.x] = in[(size_t)(r0 + threadIdx.y + i) * Ccols + c0 + threadIdx.x];
    __syncthreads();
#pragma unroll
    for (int i = 0; i < 32; i += 8)
        out[(size_t)(c0 + threadIdx.y + i) * R + r0 + threadIdx.x] =
            __float2half(tl[threadIdx.x][threadIdx.y + i]);
}

// ---------------------------------------------------------------------------
// Fused attention per (batch, head), register-blocked 4x4 per thread.
// Inputs fp16, math fp32. smem: Qs|Ks|Ss 64*65 each = 49920 B
// ---------------------------------------------------------------------------
__global__ __launch_bounds__(256) void attn_kernel(
    const __half* __restrict__ Q, const __half* __restrict__ K,
    const __half* __restrict__ V, float* __restrict__ scores,
    __half* __restrict__ O, float* __restrict__ attn_out, int has_prev)
{
    extern __shared__ float sm[];
    float* Qs = sm;
    float* Ks = sm + 4160;
    float* Ss = sm + 8320;

    const int bh = blockIdx.x;
    const int bv = bh / NHEAD, h = bh % NHEAD;
    const int row0 = bv * LSEQ, c0 = h * 64;
    const int t = threadIdx.x;
    const size_t sb = (size_t)bh * 4096;

#pragma unroll
    for (int s = 0; s < 16; s++) {
        int e = t + 256 * s;
        int i = e >> 6, kk = e & 63;
        Qs[i * 65 + kk] = __half2float(Q[(size_t)(row0 + i) * DM + c0 + kk]);
        Ks[i * 65 + kk] = __half2float(K[(size_t)(row0 + i) * DM + c0 + kk]);
    }
    __syncthreads();

    const int i0 = (t >> 4) * 4;
    const int jc = t & 15;
    float acc[4][4];
#pragma unroll
    for (int a = 0; a < 4; a++)
#pragma unroll
        for (int b = 0; b < 4; b++) acc[a][b] = 0.f;

    for (int kk = 0; kk < 64; kk++) {
        float qa[4], kb[4];
#pragma unroll
        for (int a = 0; a < 4; a++) qa[a] = Qs[(i0 + a) * 65 + kk];
#pragma unroll
        for (int b = 0; b < 4; b++) kb[b] = Ks[(jc + 16 * b) * 65 + kk];
#pragma unroll
        for (int a = 0; a < 4; a++)
#pragma unroll
            for (int b = 0; b < 4; b++) acc[a][b] += qa[a] * kb[b];
    }

#pragma unroll
    for (int a = 0; a < 4; a++) {
#pragma unroll
        for (int b = 0; b < 4; b++) {
            int i = i0 + a, j = jc + 16 * b;
            float val = acc[a][b] * 0.125f;
            if (has_prev) val += scores[sb + i * 64 + j];
            scores[sb + i * 64 + j] = val;
            Ss[i * 65 + j] = val;
        }
    }
    __syncthreads();

    const int w = t >> 5, lane = t & 31;
#pragma unroll
    for (int p = 0; p < 8; p++) {
        int r = w * 8 + p;
        float v0 = Ss[r * 65 + lane], v1 = Ss[r * 65 + lane + 32];
        float mx = fmaxf(v0, v1);
#pragma unroll
        for (int off = 16; off > 0; off >>= 1)
            mx = fmaxf(mx, __shfl_xor_sync(0xffffffffu, mx, off));
        float e0 = __expf(v0 - mx), e1 = __expf(v1 - mx);
        float sumv = e0 + e1;
#pragma unroll
        for (int off = 16; off > 0; off >>= 1)
            sumv += __shfl_xor_sync(0xffffffffu, sumv, off);
        float inv = 1.0f / sumv;
        e0 *= inv; e1 *= inv;
        Ss[r * 65 + lane] = e0;
        Ss[r * 65 + lane + 32] = e1;
        if (attn_out) {
            attn_out[sb + r * 64 + lane] = e0;
            attn_out[sb + r * 64 + lane + 32] = e1;
        }
    }
    __syncthreads();

#pragma unroll
    for (int s = 0; s < 16; s++) {
        int e = t + 256 * s;
        int i = e >> 6, kk = e & 63;
        Ks[i * 65 + kk] = __half2float(V[(size_t)(row0 + i) * DM + c0 + kk]);
    }
    __syncthreads();

    float acc2[4][4];
#pragma unroll
    for (int a = 0; a < 4; a++)
#pragma unroll
        for (int b = 0; b < 4; b++) acc2[a][b] = 0.f;

    for (int j = 0; j < 64; j++) {
        float sa[4], vb[4];
#pragma unroll
        for (int a = 0; a < 4; a++) sa[a] = Ss[(i0 + a) * 65 + j];
#pragma unroll
        for (int b = 0; b < 4; b++) vb[b] = Ks[j * 65 + jc + 16 * b];
#pragma unroll
        for (int a = 0; a < 4; a++)
#pragma unroll
            for (int b = 0; b < 4; b++) acc2[a][b] += sa[a] * vb[b];
    }

#pragma unroll
    for (int a = 0; a < 4; a++)
#pragma unroll
        for (int b = 0; b < 4; b++)
            O[(size_t)(row0 + i0 + a) * DM + c0 + jc + 16 * b] = __float2half(acc2[a][b]);
}

// ---------------------------------------------------------------------------
// BatchNorm finalize
// ---------------------------------------------------------------------------
__global__ void zero_stats_kernel(float* stats)
{
    int idx = blockIdx.x * 256 + threadIdx.x;
    if (idx < 2 * DM) stats[idx] = 0.f;
}

__global__ __launch_bounds__(256) void bn_norm_kernel(
    float* __restrict__ u, __half* __restrict__ uh, const float* __restrict__ stats,
    const float* __restrict__ g, const float* __restrict__ be)
{
    int idx = blockIdx.x * 256 + threadIdx.x;
    int c = idx % DM;
    const float invM = 1.0f / (float)MROWS;
    float mean = stats[c] * invM;
    float var = stats[DM + c] * invM - mean * mean;
    float iv = rsqrtf(var + 1e-5f);
    float val = (u[idx] - mean) * iv * g[c] + be[c];
    u[idx] = val;
    uh[idx] = __float2half(val);
}

// ---------------------------------------------------------------------------
// Misc remap / transposes
// ---------------------------------------------------------------------------
__global__ __launch_bounds__(256) void remap_embed_kernel(
    const float* __restrict__ h, const float* __restrict__ Wpos,
    float* __restrict__ u, __half* __restrict__ uh)
{
    int idx = blockIdx.x * 256 + threadIdx.x;
    int ru = idx / DM, d = idx % DM;
    int bv = ru >> 6, n = ru & 63;
    int b = bv / 7, v = bv % 7;
    int rh = (b * 64 + n) * 7 + v;
    float val = h[(size_t)rh * DM + d] + Wpos[n * DM + d];
    u[idx] = val;
    uh[idx] = __float2half(val);
}

__global__ void transpose_h_kernel(const float* __restrict__ h, float* __restrict__ out)
{
    __shared__ float tile[32][33];
    int bv = blockIdx.z, b = bv / 7, v = bv % 7;
    int d0 = blockIdx.x * 32, n0 = blockIdx.y * 32;
#pragma unroll
    for (int i = 0; i < 32; i += 8) {
        int n = n0 + threadIdx.y + i;
        int d = d0 + threadIdx.x;
        tile[threadIdx.y + i][threadIdx.x] = h[((size_t)(b * 64 + n) * 7 + v) * DM + d];
    }
    __syncthreads();
#pragma unroll
    for (int i = 0; i < 32; i += 8) {
        int d = d0 + threadIdx.y + i;
        int n = n0 + threadIdx.x;
        out[((size_t)bv * DM + d) * LSEQ + n] = tile[threadIdx.x][threadIdx.y + i];
    }
}

__global__ void transpose_z_kernel(const float* __restrict__ u, float* __restrict__ out)
{
    __shared__ float tile[32][33];
    int bv = blockIdx.z;
    int d0 = blockIdx.x * 32, n0 = blockIdx.y * 32;
#pragma unroll
    for (int i = 0; i < 32; i += 8) {
        int n = n0 + threadIdx.y + i;
        int d = d0 + threadIdx.x;
        tile[threadIdx.y + i][threadIdx.x] = u[(size_t)(bv * 64 + n) * DM + d];
    }
    __syncthreads();
#pragma unroll
    for (int i = 0; i < 32; i += 8) {
        int d = d0 + threadIdx.y + i;
        int n = n0 + threadIdx.x;
        out[((size_t)bv * DM + d) * LSEQ + n] = tile[threadIdx.x][threadIdx.y + i];
    }
}

// ---------------------------------------------------------------------------

extern "C" void kernel_launch(void* const* d_in, const int* in_sizes, int n_in,
                              void* d_out, int out_size)
{
    const float* x    = (const float*)d_in[0];
    const float* Wp   = (const float*)d_in[1];
    const float* bp   = (const float*)d_in[2];
    const float* Wpos = (const float*)d_in[3];
    const float* Wq   = (const float*)d_in[4];
    const float* bq   = (const float*)d_in[5];
    const float* Wk   = (const float*)d_in[6];
    const float* bk   = (const float*)d_in[7];
    const float* Wv   = (const float*)d_in[8];
    const float* bv_  = (const float*)d_in[9];
    const float* Wo   = (const float*)d_in[10];
    const float* bo   = (const float*)d_in[11];
    const float* g1   = (const float*)d_in[12];
    const float* be1  = (const float*)d_in[13];
    const float* W1   = (const float*)d_in[14];
    const float* b1   = (const float*)d_in[15];
    const float* W2   = (const float*)d_in[16];
    const float* b2   = (const float*)d_in[17];
    const float* g2   = (const float*)d_in[18];
    const float* be2  = (const float*)d_in[19];

    float* out      = (float*)d_out;
    float* out_z    = out;
    float* out_h    = out + OUTSZ;
    float* out_attn = out + 2 * (size_t)OUTSZ;

    float *u, *t, *sc, *st;
    __half *uh, *qh, *kh, *vh, *oh, *ffh, *wqt, *wkt, *wvt, *wot, *w1t, *w2t;
    cudaGetSymbolAddress((void**)&u,  g_u);
    cudaGetSymbolAddress((void**)&uh, g_uh);
    cudaGetSymbolAddress((void**)&qh, g_qh);
    cudaGetSymbolAddress((void**)&kh, g_kh);
    cudaGetSymbolAddress((void**)&vh, g_vh);
    cudaGetSymbolAddress((void**)&oh, g_oh);
    cudaGetSymbolAddress((void**)&t,  g_t);
    cudaGetSymbolAddress((void**)&ffh, g_ffh);
    cudaGetSymbolAddress((void**)&sc, g_scores);
    cudaGetSymbolAddress((void**)&st, g_stats);
    cudaGetSymbolAddress((void**)&wqt, g_wqt);
    cudaGetSymbolAddress((void**)&wkt, g_wkt);
    cudaGetSymbolAddress((void**)&wvt, g_wvt);
    cudaGetSymbolAddress((void**)&wot, g_wot);
    cudaGetSymbolAddress((void**)&w1t, g_w1t);
    cudaGetSymbolAddress((void**)&w2t, g_w2t);

    cudaFuncSetAttribute(attn_kernel, cudaFuncAttributeMaxDynamicSharedMemorySize, 49920);

    const dim3 blk(256);
    const int elemBlocks = (MROWS * DM) / 256;
    const dim3 tgrid(24, 2, BH);
    const dim3 tblk32(32, 8);
    const dim3 gD(DM / 128, MROWS / 128);   // (6, 224)
    const dim3 gF(DF / 128, MROWS / 128);   // (24, 224)
    const dim3 gdd(DM / 32, DM / 32);
    const dim3 g1d(DF / 32, DM / 32);
    const dim3 g2d(DM / 32, DF / 32);

    // early launches: get an hgemm near ncu's capture point
    wtrans_kernel<<<gdd, tblk32>>>(Wq, wqt, DM, DM);                                // 0
    wtrans_kernel<<<gdd, tblk32>>>(Wk, wkt, DM, DM);                                // 1
    gemm_kernel<<<dim3(DM / 128, MROWS / 128), blk>>>(x, Wp, bp, t, MROWS, DM, 16); // 2
    remap_embed_kernel<<<elemBlocks, blk>>>(t, Wpos, u, uh);                        // 3
    hgemm<0, 0, 1, 0><<<gD, blk>>>(uh, wqt, bq, nullptr, qh, nullptr, nullptr, DM, DM); // 4
    hgemm<0, 0, 1, 0><<<gD, blk>>>(uh, wkt, bk, nullptr, kh, nullptr, nullptr, DM, DM); // 5

    transpose_h_kernel<<<tgrid, tblk32>>>(t, out_h);
    wtrans_kernel<<<gdd, tblk32>>>(Wv, wvt, DM, DM);
    wtrans_kernel<<<gdd, tblk32>>>(Wo, wot, DM, DM);
    wtrans_kernel<<<g1d, tblk32>>>(W1, w1t, DM, DF);
    wtrans_kernel<<<g2d, tblk32>>>(W2, w2t, DF, DM);
    for (int l = 1; l < 3; l++) {
        wtrans_kernel<<<gdd, tblk32>>>(Wq + (size_t)l * DM * DM, wqt + (size_t)l * DM * DM, DM, DM);
        wtrans_kernel<<<gdd, tblk32>>>(Wk + (size_t)l * DM * DM, wkt + (size_t)l * DM * DM, DM, DM);
        wtrans_kernel<<<gdd, tblk32>>>(Wv + (size_t)l * DM * DM, wvt + (size_t)l * DM * DM, DM, DM);
        wtrans_kernel<<<gdd, tblk32>>>(Wo + (size_t)l * DM * DM, wot + (size_t)l * DM * DM, DM, DM);
        wtrans_kernel<<<g1d, tblk32>>>(W1 + (size_t)l * DM * DF, w1t + (size_t)l * DM * DF, DM, DF);
        wtrans_kernel<<<g2d, tblk32>>>(W2 + (size_t)l * DF * DM, w2t + (size_t)l * DF * DM, DF, DM);
    }

    for (int l = 0; l < 3; l++) {
        if (l > 0) {
            hgemm<0, 0, 1, 0><<<gD, blk>>>(uh, wqt + (size_t)l * DM * DM, bq + l * DM,
                                           nullptr, qh, nullptr, nullptr, DM, DM);
            hgemm<0, 0, 1, 0><<<gD, blk>>>(uh, wkt + (size_t)l * DM * DM, bk + l * DM,
                                           nullptr, kh, nullptr, nullptr, DM, DM);
        }
        hgemm<0, 0, 1, 0><<<gD, blk>>>(uh, wvt + (size_t)l * DM * DM, bv_ + l * DM,
                                       nullptr, vh, nullptr, nullptr, DM, DM);

        attn_kernel<<<BH * NHEAD, 256, 49920>>>(
            qh, kh, vh, sc, oh, (l == 2) ? out_attn : nullptr, (l > 0) ? 1 : 0);

        zero_stats_kernel<<<6, 256>>>(st);
        hgemm<0, 0, 0, 1><<<gD, blk>>>(oh, wot + (size_t)l * DM * DM, bo + l * DM,
                                       nullptr, nullptr, u, st, DM, DM);
        bn_norm_kernel<<<elemBlocks, blk>>>(u, uh, st, g1 + l * DM, be1 + l * DM);

        hgemm<1, 0, 1, 0><<<gF, blk>>>(uh, w1t + (size_t)l * DM * DF, b1 + l * DF,
                                       nullptr, ffh, nullptr, nullptr, DF, DM);
        zero_stats_kernel<<<6, 256>>>(st);
        hgemm<0, 0, 0, 1><<<gD, blk>>>(ffh, w2t + (size_t)l * DF * DM, b2 + l * DM,
                                       nullptr, nullptr, u, st, DM, DF);
        bn_norm_kernel<<<elemBlocks, blk>>>(u, uh, st, g2 + l * DM, be2 + l * DM);
    }

    transpose_z_kernel<<<tgrid, tblk32>>>(u, out_z);
}

// round 8
// speedup vs baseline: 1.2002x; 1.0291x over previous
#include <cuda_runtime.h>
#include <cuda_fp16.h>
#include <math.h>
#include <stdint.h>

// ---------------------------------------------------------------------------
// RockTS encoder: BS=64, NP=64, NV=7, PL=16, DM=768, NH=12, DK=64, DF=3072, NL=3
// M = 28672 rows. Outputs: z | h_t | attn concatenated in d_out.
// R8: fused QKV GEMM (N=2304), 3-stage cp.async hgemm, BN fused in epilogue.
// ---------------------------------------------------------------------------

#define MROWS 28672
#define DM    768
#define DF    3072
#define QKVN  2304
#define LSEQ  64
#define BH    448
#define NHEAD 12
#define OUTSZ 22020096

__device__ float  g_u[MROWS * DM];
__device__ __half g_uh[MROWS * DM];
__device__ __half g_qkvh[MROWS * QKVN];
__device__ __half g_oh[MROWS * DM];
__device__ float  g_t[MROWS * DM];
__device__ __half g_ffh[MROWS * DF];
__device__ float  g_scores[BH * NHEAD * LSEQ * LSEQ];
__device__ float  g_stats[2 * DM];
__device__ __half g_wqkvt[3 * QKVN * DM];   // per layer: [2304, 768] rows=outcol
__device__ float  g_bqkv[3 * QKVN];
__device__ __half g_wot[3 * DM * DM];
__device__ __half g_w1t[3 * DM * DF];
__device__ __half g_w2t[3 * DF * DM];

// ---------------------------------------------------------------------------
// fp16 MMA GEMM: C[M,N] = A[M,K] @ Bt[N,K]^T + bias
// BM=BN=128, BK=32, 8 warps (2m x 4n), warp tile 64x32, m16n8k16, ldmatrix,
// 3-stage cp.async (dynamic smem 61440 B, 2 CTAs/SM).
// RESID: C += U (residual), write U, atomic BN stats.
// ---------------------------------------------------------------------------
#define SROWH 40
#define STAGE_BYTES (128 * SROWH * 2)           // 10240 per matrix per stage
#define HG_SMEM (6 * STAGE_BYTES)               // 61440

__device__ __forceinline__ void cpasync16u(uint32_t sa, const void* gp) {
    asm volatile("cp.async.cg.shared.global [%0], [%1], 16;" :: "r"(sa), "l"(gp));
}

template<int GELU_EPI, int WRITE_F, int WRITE_H, int RESID>
__global__ __launch_bounds__(256, 2) void hgemm(
    const __half* __restrict__ A, const __half* __restrict__ Bt,
    const float* __restrict__ bias, float* __restrict__ Cf,
    __half* __restrict__ Ch, float* __restrict__ U, float* __restrict__ stats,
    int N, int K)
{
    extern __shared__ char dsm[];
    const uint32_t sbase = (uint32_t)__cvta_generic_to_shared(dsm);
    // stages: [A0 B0 A1 B1 A2 B2]
    const int tid  = threadIdx.x;
    const int wid  = tid >> 5, lane = tid & 31;
    const int g    = lane >> 2, tig = lane & 3;
    const int wm   = (wid & 1) * 64;
    const int wn   = (wid >> 1) * 32;
    const int m0   = blockIdx.y * 128, n0 = blockIdx.x * 128;
    const int NK   = K >> 5;

    const int arow  = lane & 15;
    const int akoff = (lane & 16) >> 1;
    const int nrow  = ((lane & 16) >> 1) + (lane & 7);
    const int bkoff = lane & 8;
    const uint32_t aOff = sbase + ((wm + arow) * SROWH + akoff) * 2;
    const uint32_t bOff = sbase + STAGE_BYTES + ((wn + nrow) * SROWH + bkoff) * 2;

    float acc[16][4];
#pragma unroll
    for (int i = 0; i < 16; i++)
#pragma unroll
        for (int j = 0; j < 4; j++) acc[i][j] = 0.f;

    auto load_stage = [&](int stg, int it) {
        const __half* Ab = A + (size_t)m0 * K + it * 32;
        const __half* Bb = Bt + (size_t)n0 * K + it * 32;
        uint32_t dA = sbase + stg * (2 * STAGE_BYTES);
        uint32_t dB = dA + STAGE_BYTES;
#pragma unroll
        for (int r = 0; r < 2; r++) {
            int c = tid + 256 * r;
            int row = c >> 2, cj = c & 3;
            cpasync16u(dA + (row * SROWH + cj * 8) * 2, Ab + (size_t)row * K + cj * 8);
            cpasync16u(dB + (row * SROWH + cj * 8) * 2, Bb + (size_t)row * K + cj * 8);
        }
        asm volatile("cp.async.commit_group;");
    };

    load_stage(0, 0);
    if (NK > 1) load_stage(1, 1);

    for (int it = 0; it < NK; it++) {
        const int s = it % 3;
        if (it + 2 < NK) {
            load_stage((it + 2) % 3, it + 2);
            asm volatile("cp.async.wait_group 2;");
        } else if (it + 1 < NK) {
            asm volatile("cp.async.wait_group 1;");
        } else {
            asm volatile("cp.async.wait_group 0;");
        }
        __syncthreads();

        const uint32_t aS = aOff + s * (2 * STAGE_BYTES);
        const uint32_t bS = bOff + s * (2 * STAGE_BYTES);
#pragma unroll
        for (int ks = 0; ks < 2; ks++) {
            uint32_t a[4][4], b[4][2];
#pragma unroll
            for (int mt = 0; mt < 4; mt++) {
                uint32_t ad = aS + mt * (16 * SROWH * 2) + ks * 32;
                asm volatile("ldmatrix.sync.aligned.m8n8.x4.shared.b16 {%0,%1,%2,%3}, [%4];"
                             : "=r"(a[mt][0]), "=r"(a[mt][1]), "=r"(a[mt][2]), "=r"(a[mt][3])
                             : "r"(ad));
            }
#pragma unroll
            for (int p = 0; p < 2; p++) {
                uint32_t bd = bS + p * (16 * SROWH * 2) + ks * 32;
                asm volatile("ldmatrix.sync.aligned.m8n8.x4.shared.b16 {%0,%1,%2,%3}, [%4];"
                             : "=r"(b[2 * p][0]), "=r"(b[2 * p][1]),
                               "=r"(b[2 * p + 1][0]), "=r"(b[2 * p + 1][1])
                             : "r"(bd));
            }
#pragma unroll
            for (int mt = 0; mt < 4; mt++)
#pragma unroll
                for (int nt = 0; nt < 4; nt++) {
                    float* c = acc[mt * 4 + nt];
                    asm volatile(
                        "mma.sync.aligned.m16n8k16.row.col.f32.f16.f16.f32 "
                        "{%0,%1,%2,%3}, {%4,%5,%6,%7}, {%8,%9}, {%0,%1,%2,%3};"
                        : "+f"(c[0]), "+f"(c[1]), "+f"(c[2]), "+f"(c[3])
                        : "r"(a[mt][0]), "r"(a[mt][1]), "r"(a[mt][2]), "r"(a[mt][3]),
                          "r"(b[nt][0]), "r"(b[nt][1]));
                }
        }
        __syncthreads();
    }

    // epilogue
    float cs[8], cq[8];
    if (RESID) {
#pragma unroll
        for (int i = 0; i < 8; i++) { cs[i] = 0.f; cq[i] = 0.f; }
    }
#pragma unroll
    for (int mt = 0; mt < 4; mt++) {
#pragma unroll
        for (int nt = 0; nt < 4; nt++) {
            const float* c = acc[mt * 4 + nt];
            int col = n0 + wn + nt * 8 + 2 * tig;
            float b0 = bias[col], b1 = bias[col + 1];
            int r0 = m0 + wm + mt * 16 + g;
            float2 v0, v1;
            v0.x = c[0] + b0; v0.y = c[1] + b1;
            v1.x = c[2] + b0; v1.y = c[3] + b1;
            if (GELU_EPI) {
                v0.x = 0.5f * v0.x * (1.0f + erff(v0.x * 0.70710678118654752f));
                v0.y = 0.5f * v0.y * (1.0f + erff(v0.y * 0.70710678118654752f));
                v1.x = 0.5f * v1.x * (1.0f + erff(v1.x * 0.70710678118654752f));
                v1.y = 0.5f * v1.y * (1.0f + erff(v1.y * 0.70710678118654752f));
            }
            if (RESID) {
                float2 u0 = *(float2*)&U[(size_t)r0 * N + col];
                float2 u1 = *(float2*)&U[(size_t)(r0 + 8) * N + col];
                v0.x += u0.x; v0.y += u0.y;
                v1.x += u1.x; v1.y += u1.y;
                *(float2*)&U[(size_t)r0 * N + col] = v0;
                *(float2*)&U[(size_t)(r0 + 8) * N + col] = v1;
                cs[nt * 2 + 0] += v0.x + v1.x;
                cs[nt * 2 + 1] += v0.y + v1.y;
                cq[nt * 2 + 0] += v0.x * v0.x + v1.x * v1.x;
                cq[nt * 2 + 1] += v0.y * v0.y + v1.y * v1.y;
            }
            if (WRITE_F) {
                *(float2*)&Cf[(size_t)r0 * N + col] = v0;
                *(float2*)&Cf[(size_t)(r0 + 8) * N + col] = v1;
            }
            if (WRITE_H) {
                __half2 h0, h1;
                h0.x = __float2half(v0.x); h0.y = __float2half(v0.y);
                h1.x = __float2half(v1.x); h1.y = __float2half(v1.y);
                *(__half2*)&Ch[(size_t)r0 * N + col] = h0;
                *(__half2*)&Ch[(size_t)(r0 + 8) * N + col] = h1;
            }
        }
    }
    if (RESID) {
#pragma unroll
        for (int i = 0; i < 8; i++) {
            cs[i] += __shfl_down_sync(0xffffffffu, cs[i], 16);
            cs[i] += __shfl_down_sync(0xffffffffu, cs[i], 8);
            cs[i] += __shfl_down_sync(0xffffffffu, cs[i], 4);
            cq[i] += __shfl_down_sync(0xffffffffu, cq[i], 16);
            cq[i] += __shfl_down_sync(0xffffffffu, cq[i], 8);
            cq[i] += __shfl_down_sync(0xffffffffu, cq[i], 4);
        }
        if (lane < 4) {
#pragma unroll
            for (int nt = 0; nt < 4; nt++) {
                int col = n0 + wn + nt * 8 + 2 * tig;
                atomicAdd(&stats[col],     cs[nt * 2 + 0]);
                atomicAdd(&stats[col + 1], cs[nt * 2 + 1]);
                atomicAdd(&stats[DM + col],     cq[nt * 2 + 0]);
                atomicAdd(&stats[DM + col + 1], cq[nt * 2 + 1]);
            }
        }
    }
}

// ---------------------------------------------------------------------------
// fp32 SGEMM (patch embed, K=16)
// ---------------------------------------------------------------------------
__global__ __launch_bounds__(256, 2) void gemm_kernel(
    const float* __restrict__ A, const float* __restrict__ B,
    const float* __restrict__ bias, float* __restrict__ C,
    int Mdim, int Ndim, int Kdim)
{
    __shared__ float As[16][128];
    __shared__ float Bs[16][132];
    const int tid = threadIdx.x;
    const int tx = tid & 15, ty = tid >> 4;
    const int m0 = blockIdx.y * 128, n0 = blockIdx.x * 128;
    float acc[8][8];
#pragma unroll
    for (int i = 0; i < 8; i++)
#pragma unroll
        for (int j = 0; j < 8; j++) acc[i][j] = 0.f;
    for (int k0 = 0; k0 < Kdim; k0 += 16) {
#pragma unroll
        for (int s = 0; s < 2; s++) {
            int f4 = tid + 256 * s;
            int row = f4 >> 2, kq = (f4 & 3) * 4;
            float4 av = *(const float4*)&A[(size_t)(m0 + row) * Kdim + k0 + kq];
            As[kq + 0][row] = av.x; As[kq + 1][row] = av.y;
            As[kq + 2][row] = av.z; As[kq + 3][row] = av.w;
        }
#pragma unroll
        for (int s = 0; s < 2; s++) {
            int f4 = tid + 256 * s;
            int row = f4 >> 5, nq = (f4 & 31) * 4;
            *(float4*)&Bs[row][nq] = *(const float4*)&B[(size_t)(k0 + row) * Ndim + n0 + nq];
        }
        __syncthreads();
#pragma unroll
        for (int k = 0; k < 16; k++) {
            float a[8], b[8];
            *(float4*)&a[0] = *(const float4*)&As[k][ty * 8];
            *(float4*)&a[4] = *(const float4*)&As[k][ty * 8 + 4];
            *(float4*)&b[0] = *(const float4*)&Bs[k][tx * 8];
            *(float4*)&b[4] = *(const float4*)&Bs[k][tx * 8 + 4];
#pragma unroll
            for (int i = 0; i < 8; i++)
#pragma unroll
                for (int j = 0; j < 8; j++) acc[i][j] += a[i] * b[j];
        }
        __syncthreads();
    }
#pragma unroll
    for (int i = 0; i < 8; i++) {
        int row = m0 + ty * 8 + i;
#pragma unroll
        for (int j = 0; j < 8; j++) {
            int col = n0 + tx * 8 + j;
            C[(size_t)row * Ndim + col] = acc[i][j] + bias[col];
        }
    }
}

// ---------------------------------------------------------------------------
// Weight transpose + fp16 convert: out[N,K] = half(in[K,N]^T)
// ---------------------------------------------------------------------------
__global__ void wtrans_kernel(const float* __restrict__ in, __half* __restrict__ out,
                              int R, int Ccols)
{
    __shared__ float tl[32][33];
    int c0 = blockIdx.x * 32, r0 = blockIdx.y * 32;
#pragma unroll
    for (int i = 0; i < 32; i += 8)
        tl[threadIdx.y + i][threadIdx.x] = in[(size_t)(r0 + threadIdx.y + i) * Ccols + c0 + threadIdx.x];
    __syncthreads();
#pragma unroll
    for (int i = 0; i < 32; i += 8)
        out[(size_t)(c0 + threadIdx.y + i) * R + r0 + threadIdx.x] =
            __float2half(tl[threadIdx.x][threadIdx.y + i]);
}

// concat QKV bias into [NL, 2304]
__global__ void bias_concat_kernel(const float* __restrict__ bq, const float* __restrict__ bk,
                                   const float* __restrict__ bv, float* __restrict__ bqkv)
{
    int idx = blockIdx.x * 256 + threadIdx.x;
    if (idx >= 3 * QKVN) return;
    int l = idx / QKVN, c = idx % QKVN;
    int sec = c / DM, cc = c % DM;
    const float* src = (sec == 0) ? bq : (sec == 1) ? bk : bv;
    bqkv[idx] = src[l * DM + cc];
}

// ---------------------------------------------------------------------------
// Fused attention per (batch, head), register-blocked 4x4 per thread.
// QKV packed [row, 2304]: Q at +0, K at +768, V at +1536 (per-head 64 cols).
// ---------------------------------------------------------------------------
__global__ __launch_bounds__(256) void attn_kernel(
    const __half* __restrict__ QKV, float* __restrict__ scores,
    __half* __restrict__ O, float* __restrict__ attn_out, int has_prev)
{
    extern __shared__ float sm[];
    float* Qs = sm;
    float* Ks = sm + 4160;
    float* Ss = sm + 8320;

    const int bh = blockIdx.x;
    const int bv = bh / NHEAD, h = bh % NHEAD;
    const int row0 = bv * LSEQ, c0 = h * 64;
    const int t = threadIdx.x;
    const size_t sb = (size_t)bh * 4096;

#pragma unroll
    for (int s = 0; s < 16; s++) {
        int e = t + 256 * s;
        int i = e >> 6, kk = e & 63;
        Qs[i * 65 + kk] = __half2float(QKV[(size_t)(row0 + i) * QKVN + c0 + kk]);
        Ks[i * 65 + kk] = __half2float(QKV[(size_t)(row0 + i) * QKVN + DM + c0 + kk]);
    }
    __syncthreads();

    const int i0 = (t >> 4) * 4;
    const int jc = t & 15;
    float acc[4][4];
#pragma unroll
    for (int a = 0; a < 4; a++)
#pragma unroll
        for (int b = 0; b < 4; b++) acc[a][b] = 0.f;

    for (int kk = 0; kk < 64; kk++) {
        float qa[4], kb[4];
#pragma unroll
        for (int a = 0; a < 4; a++) qa[a] = Qs[(i0 + a) * 65 + kk];
#pragma unroll
        for (int b = 0; b < 4; b++) kb[b] = Ks[(jc + 16 * b) * 65 + kk];
#pragma unroll
        for (int a = 0; a < 4; a++)
#pragma unroll
            for (int b = 0; b < 4; b++) acc[a][b] += qa[a] * kb[b];
    }

#pragma unroll
    for (int a = 0; a < 4; a++) {
#pragma unroll
        for (int b = 0; b < 4; b++) {
            int i = i0 + a, j = jc + 16 * b;
            float val = acc[a][b] * 0.125f;
            if (has_prev) val += scores[sb + i * 64 + j];
            scores[sb + i * 64 + j] = val;
            Ss[i * 65 + j] = val;
        }
    }
    __syncthreads();

    const int w = t >> 5, lane = t & 31;
#pragma unroll
    for (int p = 0; p < 8; p++) {
        int r = w * 8 + p;
        float v0 = Ss[r * 65 + lane], v1 = Ss[r * 65 + lane + 32];
        float mx = fmaxf(v0, v1);
#pragma unroll
        for (int off = 16; off > 0; off >>= 1)
            mx = fmaxf(mx, __shfl_xor_sync(0xffffffffu, mx, off));
        float e0 = __expf(v0 - mx), e1 = __expf(v1 - mx);
        float sumv = e0 + e1;
#pragma unroll
        for (int off = 16; off > 0; off >>= 1)
            sumv += __shfl_xor_sync(0xffffffffu, sumv, off);
        float inv = 1.0f / sumv;
        e0 *= inv; e1 *= inv;
        Ss[r * 65 + lane] = e0;
        Ss[r * 65 + lane + 32] = e1;
        if (attn_out) {
            attn_out[sb + r * 64 + lane] = e0;
            attn_out[sb + r * 64 + lane + 32] = e1;
        }
    }
    __syncthreads();

#pragma unroll
    for (int s = 0; s < 16; s++) {
        int e = t + 256 * s;
        int i = e >> 6, kk = e & 63;
        Ks[i * 65 + kk] = __half2float(QKV[(size_t)(row0 + i) * QKVN + 2 * DM + c0 + kk]);
    }
    __syncthreads();

    float acc2[4][4];
#pragma unroll
    for (int a = 0; a < 4; a++)
#pragma unroll
        for (int b = 0; b < 4; b++) acc2[a][b] = 0.f;

    for (int j = 0; j < 64; j++) {
        float sa[4], vb[4];
#pragma unroll
        for (int a = 0; a < 4; a++) sa[a] = Ss[(i0 + a) * 65 + j];
#pragma unroll
        for (int b = 0; b < 4; b++) vb[b] = Ks[j * 65 + jc + 16 * b];
#pragma unroll
        for (int a = 0; a < 4; a++)
#pragma unroll
            for (int b = 0; b < 4; b++) acc2[a][b] += sa[a] * vb[b];
    }

#pragma unroll
    for (int a = 0; a < 4; a++)
#pragma unroll
        for (int b = 0; b < 4; b++)
            O[(size_t)(row0 + i0 + a) * DM + c0 + jc + 16 * b] = __float2half(acc2[a][b]);
}

// ---------------------------------------------------------------------------
// BatchNorm finalize
// ---------------------------------------------------------------------------
__global__ void zero_stats_kernel(float* stats)
{
    int idx = blockIdx.x * 256 + threadIdx.x;
    if (idx < 2 * DM) stats[idx] = 0.f;
}

__global__ __launch_bounds__(256) void bn_norm_kernel(
    float* __restrict__ u, __half* __restrict__ uh, const float* __restrict__ stats,
    const float* __restrict__ g, const float* __restrict__ be)
{
    int idx = blockIdx.x * 256 + threadIdx.x;
    int c = idx % DM;
    const float invM = 1.0f / (float)MROWS;
    float mean = stats[c] * invM;
    float var = stats[DM + c] * invM - mean * mean;
    float iv = rsqrtf(var + 1e-5f);
    float val = (u[idx] - mean) * iv * g[c] + be[c];
    u[idx] = val;
    uh[idx] = __float2half(val);
}

// ---------------------------------------------------------------------------
// Misc remap / transposes
// ---------------------------------------------------------------------------
__global__ __launch_bounds__(256) void remap_embed_kernel(
    const float* __restrict__ h, const float* __restrict__ Wpos,
    float* __restrict__ u, __half* __restrict__ uh)
{
    int idx = blockIdx.x * 256 + threadIdx.x;
    int ru = idx / DM, d = idx % DM;
    int bv = ru >> 6, n = ru & 63;
    int b = bv / 7, v = bv % 7;
    int rh = (b * 64 + n) * 7 + v;
    float val = h[(size_t)rh * DM + d] + Wpos[n * DM + d];
    u[idx] = val;
    uh[idx] = __float2half(val);
}

__global__ void transpose_h_kernel(const float* __restrict__ h, float* __restrict__ out)
{
    __shared__ float tile[32][33];
    int bv = blockIdx.z, b = bv / 7, v = bv % 7;
    int d0 = blockIdx.x * 32, n0 = blockIdx.y * 32;
#pragma unroll
    for (int i = 0; i < 32; i += 8) {
        int n = n0 + threadIdx.y + i;
        int d = d0 + threadIdx.x;
        tile[threadIdx.y + i][threadIdx.x] = h[((size_t)(b * 64 + n) * 7 + v) * DM + d];
    }
    __syncthreads();
#pragma unroll
    for (int i = 0; i < 32; i += 8) {
        int d = d0 + threadIdx.y + i;
        int n = n0 + threadIdx.x;
        out[((size_t)bv * DM + d) * LSEQ + n] = tile[threadIdx.x][threadIdx.y + i];
    }
}

__global__ void transpose_z_kernel(const float* __restrict__ u, float* __restrict__ out)
{
    __shared__ float tile[32][33];
    int bv = blockIdx.z;
    int d0 = blockIdx.x * 32, n0 = blockIdx.y * 32;
#pragma unroll
    for (int i = 0; i < 32; i += 8) {
        int n = n0 + threadIdx.y + i;
        int d = d0 + threadIdx.x;
        tile[threadIdx.y + i][threadIdx.x] = u[(size_t)(bv * 64 + n) * DM + d];
    }
    __syncthreads();
#pragma unroll
    for (int i = 0; i < 32; i += 8) {
        int d = d0 + threadIdx.y + i;
        int n = n0 + threadIdx.x;
        out[((size_t)bv * DM + d) * LSEQ + n] = tile[threadIdx.x][threadIdx.y + i];
    }
}

// ---------------------------------------------------------------------------

extern "C" void kernel_launch(void* const* d_in, const int* in_sizes, int n_in,
                              void* d_out, int out_size)
{
    const float* x    = (const float*)d_in[0];
    const float* Wp   = (const float*)d_in[1];
    const float* bp   = (const float*)d_in[2];
    const float* Wpos = (const float*)d_in[3];
    const float* Wq   = (const float*)d_in[4];
    const float* bq   = (const float*)d_in[5];
    const float* Wk   = (const float*)d_in[6];
    const float* bk   = (const float*)d_in[7];
    const float* Wv   = (const float*)d_in[8];
    const float* bv_  = (const float*)d_in[9];
    const float* Wo   = (const float*)d_in[10];
    const float* bo   = (const float*)d_in[11];
    const float* g1   = (const float*)d_in[12];
    const float* be1  = (const float*)d_in[13];
    const float* W1   = (const float*)d_in[14];
    const float* b1   = (const float*)d_in[15];
    const float* W2   = (const float*)d_in[16];
    const float* b2   = (const float*)d_in[17];
    const float* g2   = (const float*)d_in[18];
    const float* be2  = (const float*)d_in[19];

    float* out      = (float*)d_out;
    float* out_z    = out;
    float* out_h    = out + OUTSZ;
    float* out_attn = out + 2 * (size_t)OUTSZ;

    float *u, *t, *sc, *st, *bqkv;
    __half *uh, *qkvh, *oh, *ffh, *wqkvt, *wot, *w1t, *w2t;
    cudaGetSymbolAddress((void**)&u,  g_u);
    cudaGetSymbolAddress((void**)&uh, g_uh);
    cudaGetSymbolAddress((void**)&qkvh, g_qkvh);
    cudaGetSymbolAddress((void**)&oh, g_oh);
    cudaGetSymbolAddress((void**)&t,  g_t);
    cudaGetSymbolAddress((void**)&ffh, g_ffh);
    cudaGetSymbolAddress((void**)&sc, g_scores);
    cudaGetSymbolAddress((void**)&st, g_stats);
    cudaGetSymbolAddress((void**)&bqkv, g_bqkv);
    cudaGetSymbolAddress((void**)&wqkvt, g_wqkvt);
    cudaGetSymbolAddress((void**)&wot, g_wot);
    cudaGetSymbolAddress((void**)&w1t, g_w1t);
    cudaGetSymbolAddress((void**)&w2t, g_w2t);

    cudaFuncSetAttribute(attn_kernel, cudaFuncAttributeMaxDynamicSharedMemorySize, 49920);
    cudaFuncSetAttribute(hgemm<0, 0, 1, 0>, cudaFuncAttributeMaxDynamicSharedMemorySize, HG_SMEM);
    cudaFuncSetAttribute(hgemm<0, 0, 0, 1>, cudaFuncAttributeMaxDynamicSharedMemorySize, HG_SMEM);
    cudaFuncSetAttribute(hgemm<1, 0, 1, 0>, cudaFuncAttributeMaxDynamicSharedMemorySize, HG_SMEM);

    const dim3 blk(256);
    const int elemBlocks = (MROWS * DM) / 256;
    const dim3 tgrid(24, 2, BH);
    const dim3 tblk32(32, 8);
    const dim3 gQKV(QKVN / 128, MROWS / 128);  // (18, 224)
    const dim3 gD(DM / 128, MROWS / 128);      // (6, 224)
    const dim3 gF(DF / 128, MROWS / 128);      // (24, 224)
    const dim3 gdd(DM / 32, DM / 32);
    const dim3 g1d(DF / 32, DM / 32);
    const dim3 g2d(DM / 32, DF / 32);

    // prologue: weights, bias concat, patch embedding
    bias_concat_kernel<<<27, 256>>>(bq, bk, bv_, bqkv);
    gemm_kernel<<<dim3(DM / 128, MROWS / 128), blk>>>(x, Wp, bp, t, MROWS, DM, 16);
    remap_embed_kernel<<<elemBlocks, blk>>>(t, Wpos, u, uh);
    transpose_h_kernel<<<tgrid, tblk32>>>(t, out_h);
    for (int l = 0; l < 3; l++) {
        __half* wl = wqkvt + (size_t)l * QKVN * DM;
        wtrans_kernel<<<gdd, tblk32>>>(Wq + (size_t)l * DM * DM, wl, DM, DM);
        wtrans_kernel<<<gdd, tblk32>>>(Wk + (size_t)l * DM * DM, wl + (size_t)DM * DM, DM, DM);
        wtrans_kernel<<<gdd, tblk32>>>(Wv + (size_t)l * DM * DM, wl + (size_t)2 * DM * DM, DM, DM);
        wtrans_kernel<<<gdd, tblk32>>>(Wo + (size_t)l * DM * DM, wot + (size_t)l * DM * DM, DM, DM);
        wtrans_kernel<<<g1d, tblk32>>>(W1 + (size_t)l * DM * DF, w1t + (size_t)l * DM * DF, DM, DF);
        wtrans_kernel<<<g2d, tblk32>>>(W2 + (size_t)l * DF * DM, w2t + (size_t)l * DF * DM, DF, DM);
    }

    for (int l = 0; l < 3; l++) {
        // fused QKV projection: N = 2304
        hgemm<0, 0, 1, 0><<<gQKV, blk, HG_SMEM>>>(
            uh, wqkvt + (size_t)l * QKVN * DM, bqkv + l * QKVN,
            nullptr, qkvh, nullptr, nullptr, QKVN, DM);

        attn_kernel<<<BH * NHEAD, 256, 49920>>>(
            qkvh, sc, oh, (l == 2) ? out_attn : nullptr, (l > 0) ? 1 : 0);

        zero_stats_kernel<<<6, 256>>>(st);
        hgemm<0, 0, 0, 1><<<gD, blk, HG_SMEM>>>(oh, wot + (size_t)l * DM * DM, bo + l * DM,
                                                nullptr, nullptr, u, st, DM, DM);
        bn_norm_kernel<<<elemBlocks, blk>>>(u, uh, st, g1 + l * DM, be1 + l * DM);

        hgemm<1, 0, 1, 0><<<gF, blk, HG_SMEM>>>(uh, w1t + (size_t)l * DM * DF, b1 + l * DF,
                                                nullptr, ffh, nullptr, nullptr, DF, DM);
        zero_stats_kernel<<<6, 256>>>(st);
        hgemm<0, 0, 0, 1><<<gD, blk, HG_SMEM>>>(ffh, w2t + (size_t)l * DF * DM, b2 + l * DM,
                                                nullptr, nullptr, u, st, DM, DF);
        bn_norm_kernel<<<elemBlocks, blk>>>(u, uh, st, g2 + l * DM, be2 + l * DM);
    }

    transpose_z_kernel<<<tgrid, tblk32>>>(u, out_z);
}

// round 9
// speedup vs baseline: 1.2503x; 1.0417x over previous
#include <cuda_runtime.h>
#include <cuda_fp16.h>
#include <math.h>
#include <stdint.h>

// ---------------------------------------------------------------------------
// RockTS encoder: BS=64, NP=64, NV=7, PL=16, DM=768, NH=12, DK=64, DF=3072, NL=3
// M = 28672 rows. Outputs: z | h_t | attn concatenated in d_out.
// R9: 4-stage 1-sync hgemm; QKV-hgemm at launch #3 (profiled); final BN folded
//     into transpose_z.
// ---------------------------------------------------------------------------

#define MROWS 28672
#define DM    768
#define DF    3072
#define QKVN  2304
#define LSEQ  64
#define BH    448
#define NHEAD 12
#define OUTSZ 22020096

__device__ float  g_u[MROWS * DM];
__device__ __half g_uh[MROWS * DM];
__device__ __half g_qkvh[MROWS * QKVN];
__device__ __half g_oh[MROWS * DM];
__device__ float  g_t[MROWS * DM];
__device__ __half g_ffh[MROWS * DF];
__device__ float  g_scores[BH * NHEAD * LSEQ * LSEQ];
__device__ float  g_stats[2 * DM];
__device__ __half g_wqkvt[3 * QKVN * DM];
__device__ float  g_bqkv[3 * QKVN];
__device__ __half g_wot[3 * DM * DM];
__device__ __half g_w1t[3 * DM * DF];
__device__ __half g_w2t[3 * DF * DM];

// ---------------------------------------------------------------------------
// fp16 MMA GEMM: C[M,N] = A[M,K] @ Bt[N,K]^T + bias
// BM=BN=128, BK=32, 8 warps (2m x 4n), warp tile 64x32, m16n8k16, ldmatrix,
// 4-stage cp.async, ONE __syncthreads per iteration. smem 81920 B, 2 CTAs/SM.
// RESID: C += U (residual), write U, atomic BN stats.
// ---------------------------------------------------------------------------
#define SROWH 40
#define STAGE_BYTES (128 * SROWH * 2)      // 10240 per matrix per stage
#define HG_SMEM (4 * 2 * STAGE_BYTES)      // 81920

__device__ __forceinline__ void cpasync16u(uint32_t sa, const void* gp) {
    asm volatile("cp.async.cg.shared.global [%0], [%1], 16;" :: "r"(sa), "l"(gp));
}

template<int GELU_EPI, int WRITE_F, int WRITE_H, int RESID>
__global__ __launch_bounds__(256, 2) void hgemm(
    const __half* __restrict__ A, const __half* __restrict__ Bt,
    const float* __restrict__ bias, float* __restrict__ Cf,
    __half* __restrict__ Ch, float* __restrict__ U, float* __restrict__ stats,
    int N, int K)
{
    extern __shared__ char dsm[];
    const uint32_t sbase = (uint32_t)__cvta_generic_to_shared(dsm);
    const int tid  = threadIdx.x;
    const int wid  = tid >> 5, lane = tid & 31;
    const int g    = lane >> 2, tig = lane & 3;
    const int wm   = (wid & 1) * 64;
    const int wn   = (wid >> 1) * 32;
    const int m0   = blockIdx.y * 128, n0 = blockIdx.x * 128;
    const int NK   = K >> 5;

    const int arow  = lane & 15;
    const int akoff = (lane & 16) >> 1;
    const int nrow  = ((lane & 16) >> 1) + (lane & 7);
    const int bkoff = lane & 8;
    const uint32_t aOff = sbase + ((wm + arow) * SROWH + akoff) * 2;
    const uint32_t bOff = sbase + STAGE_BYTES + ((wn + nrow) * SROWH + bkoff) * 2;

    float acc[16][4];
#pragma unroll
    for (int i = 0; i < 16; i++)
#pragma unroll
        for (int j = 0; j < 4; j++) acc[i][j] = 0.f;

    auto load_stage = [&](int stg, int it) {
        const __half* Ab = A + (size_t)m0 * K + it * 32;
        const __half* Bb = Bt + (size_t)n0 * K + it * 32;
        uint32_t dA = sbase + stg * (2 * STAGE_BYTES);
        uint32_t dB = dA + STAGE_BYTES;
#pragma unroll
        for (int r = 0; r < 2; r++) {
            int c = tid + 256 * r;
            int row = c >> 2, cj = c & 3;
            cpasync16u(dA + (row * SROWH + cj * 8) * 2, Ab + (size_t)row * K + cj * 8);
            cpasync16u(dB + (row * SROWH + cj * 8) * 2, Bb + (size_t)row * K + cj * 8);
        }
        asm volatile("cp.async.commit_group;");
    };

    load_stage(0, 0);
    if (NK > 1) load_stage(1, 1);
    if (NK > 2) load_stage(2, 2);

    for (int it = 0; it < NK; it++) {
        const int s = it & 3;
        if (it + 2 < NK)      asm volatile("cp.async.wait_group 2;");
        else if (it + 1 < NK) asm volatile("cp.async.wait_group 1;");
        else                  asm volatile("cp.async.wait_group 0;");
        __syncthreads();
        if (it + 3 < NK) load_stage((it + 3) & 3, it + 3);

        const uint32_t aS = aOff + s * (2 * STAGE_BYTES);
        const uint32_t bS = bOff + s * (2 * STAGE_BYTES);
#pragma unroll
        for (int ks = 0; ks < 2; ks++) {
            uint32_t a[4][4], b[4][2];
#pragma unroll
            for (int mt = 0; mt < 4; mt++) {
                uint32_t ad = aS + mt * (16 * SROWH * 2) + ks * 32;
                asm volatile("ldmatrix.sync.aligned.m8n8.x4.shared.b16 {%0,%1,%2,%3}, [%4];"
                             : "=r"(a[mt][0]), "=r"(a[mt][1]), "=r"(a[mt][2]), "=r"(a[mt][3])
                             : "r"(ad));
            }
#pragma unroll
            for (int p = 0; p < 2; p++) {
                uint32_t bd = bS + p * (16 * SROWH * 2) + ks * 32;
                asm volatile("ldmatrix.sync.aligned.m8n8.x4.shared.b16 {%0,%1,%2,%3}, [%4];"
                             : "=r"(b[2 * p][0]), "=r"(b[2 * p][1]),
                               "=r"(b[2 * p + 1][0]), "=r"(b[2 * p + 1][1])
                             : "r"(bd));
            }
#pragma unroll
            for (int mt = 0; mt < 4; mt++)
#pragma unroll
                for (int nt = 0; nt < 4; nt++) {
                    float* c = acc[mt * 4 + nt];
                    asm volatile(
                        "mma.sync.aligned.m16n8k16.row.col.f32.f16.f16.f32 "
                        "{%0,%1,%2,%3}, {%4,%5,%6,%7}, {%8,%9}, {%0,%1,%2,%3};"
                        : "+f"(c[0]), "+f"(c[1]), "+f"(c[2]), "+f"(c[3])
                        : "r"(a[mt][0]), "r"(a[mt][1]), "r"(a[mt][2]), "r"(a[mt][3]),
                          "r"(b[nt][0]), "r"(b[nt][1]));
                }
        }
    }

    // epilogue
    float cs[8], cq[8];
    if (RESID) {
#pragma unroll
        for (int i = 0; i < 8; i++) { cs[i] = 0.f; cq[i] = 0.f; }
    }
#pragma unroll
    for (int mt = 0; mt < 4; mt++) {
#pragma unroll
        for (int nt = 0; nt < 4; nt++) {
            const float* c = acc[mt * 4 + nt];
            int col = n0 + wn + nt * 8 + 2 * tig;
            float b0 = bias[col], b1 = bias[col + 1];
            int r0 = m0 + wm + mt * 16 + g;
            float2 v0, v1;
            v0.x = c[0] + b0; v0.y = c[1] + b1;
            v1.x = c[2] + b0; v1.y = c[3] + b1;
            if (GELU_EPI) {
                v0.x = 0.5f * v0.x * (1.0f + erff(v0.x * 0.70710678118654752f));
                v0.y = 0.5f * v0.y * (1.0f + erff(v0.y * 0.70710678118654752f));
                v1.x = 0.5f * v1.x * (1.0f + erff(v1.x * 0.70710678118654752f));
                v1.y = 0.5f * v1.y * (1.0f + erff(v1.y * 0.70710678118654752f));
            }
            if (RESID) {
                float2 u0 = *(float2*)&U[(size_t)r0 * N + col];
                float2 u1 = *(float2*)&U[(size_t)(r0 + 8) * N + col];
                v0.x += u0.x; v0.y += u0.y;
                v1.x += u1.x; v1.y += u1.y;
                *(float2*)&U[(size_t)r0 * N + col] = v0;
                *(float2*)&U[(size_t)(r0 + 8) * N + col] = v1;
                cs[nt * 2 + 0] += v0.x + v1.x;
                cs[nt * 2 + 1] += v0.y + v1.y;
                cq[nt * 2 + 0] += v0.x * v0.x + v1.x * v1.x;
                cq[nt * 2 + 1] += v0.y * v0.y + v1.y * v1.y;
            }
            if (WRITE_F) {
                *(float2*)&Cf[(size_t)r0 * N + col] = v0;
                *(float2*)&Cf[(size_t)(r0 + 8) * N + col] = v1;
            }
            if (WRITE_H) {
                __half2 h0, h1;
                h0.x = __float2half(v0.x); h0.y = __float2half(v0.y);
                h1.x = __float2half(v1.x); h1.y = __float2half(v1.y);
                *(__half2*)&Ch[(size_t)r0 * N + col] = h0;
                *(__half2*)&Ch[(size_t)(r0 + 8) * N + col] = h1;
            }
        }
    }
    if (RESID) {
#pragma unroll
        for (int i = 0; i < 8; i++) {
            cs[i] += __shfl_down_sync(0xffffffffu, cs[i], 16);
            cs[i] += __shfl_down_sync(0xffffffffu, cs[i], 8);
            cs[i] += __shfl_down_sync(0xffffffffu, cs[i], 4);
            cq[i] += __shfl_down_sync(0xffffffffu, cq[i], 16);
            cq[i] += __shfl_down_sync(0xffffffffu, cq[i], 8);
            cq[i] += __shfl_down_sync(0xffffffffu, cq[i], 4);
        }
        if (lane < 4) {
#pragma unroll
            for (int nt = 0; nt < 4; nt++) {
                int col = n0 + wn + nt * 8 + 2 * tig;
                atomicAdd(&stats[col],     cs[nt * 2 + 0]);
                atomicAdd(&stats[col + 1], cs[nt * 2 + 1]);
                atomicAdd(&stats[DM + col],     cq[nt * 2 + 0]);
                atomicAdd(&stats[DM + col + 1], cq[nt * 2 + 1]);
            }
        }
    }
}

// ---------------------------------------------------------------------------
// fp32 SGEMM (patch embed, K=16)
// ---------------------------------------------------------------------------
__global__ __launch_bounds__(256, 2) void gemm_kernel(
    const float* __restrict__ A, const float* __restrict__ B,
    const float* __restrict__ bias, float* __restrict__ C,
    int Mdim, int Ndim, int Kdim)
{
    __shared__ float As[16][128];
    __shared__ float Bs[16][132];
    const int tid = threadIdx.x;
    const int tx = tid & 15, ty = tid >> 4;
    const int m0 = blockIdx.y * 128, n0 = blockIdx.x * 128;
    float acc[8][8];
#pragma unroll
    for (int i = 0; i < 8; i++)
#pragma unroll
        for (int j = 0; j < 8; j++) acc[i][j] = 0.f;
    for (int k0 = 0; k0 < Kdim; k0 += 16) {
#pragma unroll
        for (int s = 0; s < 2; s++) {
            int f4 = tid + 256 * s;
            int row = f4 >> 2, kq = (f4 & 3) * 4;
            float4 av = *(const float4*)&A[(size_t)(m0 + row) * Kdim + k0 + kq];
            As[kq + 0][row] = av.x; As[kq + 1][row] = av.y;
            As[kq + 2][row] = av.z; As[kq + 3][row] = av.w;
        }
#pragma unroll
        for (int s = 0; s < 2; s++) {
            int f4 = tid + 256 * s;
            int row = f4 >> 5, nq = (f4 & 31) * 4;
            *(float4*)&Bs[row][nq] = *(const float4*)&B[(size_t)(k0 + row) * Ndim + n0 + nq];
        }
        __syncthreads();
#pragma unroll
        for (int k = 0; k < 16; k++) {
            float a[8], b[8];
            *(float4*)&a[0] = *(const float4*)&As[k][ty * 8];
            *(float4*)&a[4] = *(const float4*)&As[k][ty * 8 + 4];
            *(float4*)&b[0] = *(const float4*)&Bs[k][tx * 8];
            *(float4*)&b[4] = *(const float4*)&Bs[k][tx * 8 + 4];
#pragma unroll
            for (int i = 0; i < 8; i++)
#pragma unroll
                for (int j = 0; j < 8; j++) acc[i][j] += a[i] * b[j];
        }
        __syncthreads();
    }
#pragma unroll
    for (int i = 0; i < 8; i++) {
        int row = m0 + ty * 8 + i;
#pragma unroll
        for (int j = 0; j < 8; j++) {
            int col = n0 + tx * 8 + j;
            C[(size_t)row * Ndim + col] = acc[i][j] + bias[col];
        }
    }
}

// ---------------------------------------------------------------------------
// QKV weight transpose (one layer in one launch) + bias concat (z==3 plane)
// wout[2304,768] = [Wq^T; Wk^T; Wv^T], bout[2304] = [bq; bk; bv]
// ---------------------------------------------------------------------------
__global__ void qkv_wtrans_kernel(
    const float* __restrict__ Wq, const float* __restrict__ Wk,
    const float* __restrict__ Wv, const float* __restrict__ bq,
    const float* __restrict__ bk, const float* __restrict__ bv,
    __half* __restrict__ wout, float* __restrict__ bout)
{
    int z = blockIdx.z;
    if (z == 3) {
        int idx = (blockIdx.y * gridDim.x + blockIdx.x) * 256 +
                  threadIdx.y * 32 + threadIdx.x;
        if (idx < QKVN) {
            int sec = idx / DM, cc = idx % DM;
            const float* src = (sec == 0) ? bq : (sec == 1) ? bk : bv;
            bout[idx] = src[cc];
        }
        return;
    }
    const float* W = (z == 0) ? Wq : (z == 1) ? Wk : Wv;
    __shared__ float tl[32][33];
    int c0 = blockIdx.x * 32, r0 = blockIdx.y * 32;
#pragma unroll
    for (int i = 0; i < 32; i += 8)
        tl[threadIdx.y + i][threadIdx.x] = W[(size_t)(r0 + threadIdx.y + i) * DM + c0 + threadIdx.x];
    __syncthreads();
#pragma unroll
    for (int i = 0; i < 32; i += 8)
        wout[(size_t)(z * DM + c0 + threadIdx.y + i) * DM + r0 + threadIdx.x] =
            __float2half(tl[threadIdx.x][threadIdx.y + i]);
}

// generic weight transpose
__global__ void wtrans_kernel(const float* __restrict__ in, __half* __restrict__ out,
                              int R, int Ccols)
{
    __shared__ float tl[32][33];
    int c0 = blockIdx.x * 32, r0 = blockIdx.y * 32;
#pragma unroll
    for (int i = 0; i < 32; i += 8)
        tl[threadIdx.y + i][threadIdx.x] = in[(size_t)(r0 + threadIdx.y + i) * Ccols + c0 + threadIdx.x];
    __syncthreads();
#pragma unroll
    for (int i = 0; i < 32; i += 8)
        out[(size_t)(c0 + threadIdx.y + i) * R + r0 + threadIdx.x] =
            __float2half(tl[threadIdx.x][threadIdx.y + i]);
}

// ---------------------------------------------------------------------------
// Fused attention per (batch, head). QKV packed [row, 2304].
// ---------------------------------------------------------------------------
__global__ __launch_bounds__(256) void attn_kernel(
    const __half* __restrict__ QKV, float* __restrict__ scores,
    __half* __restrict__ O, float* __restrict__ attn_out, int has_prev)
{
    extern __shared__ float sm[];
    float* Qs = sm;
    float* Ks = sm + 4160;
    float* Ss = sm + 8320;

    const int bh = blockIdx.x;
    const int bv = bh / NHEAD, h = bh % NHEAD;
    const int row0 = bv * LSEQ, c0 = h * 64;
    const int t = threadIdx.x;
    const size_t sb = (size_t)bh * 4096;

#pragma unroll
    for (int s = 0; s < 16; s++) {
        int e = t + 256 * s;
        int i = e >> 6, kk = e & 63;
        Qs[i * 65 + kk] = __half2float(QKV[(size_t)(row0 + i) * QKVN + c0 + kk]);
        Ks[i * 65 + kk] = __half2float(QKV[(size_t)(row0 + i) * QKVN + DM + c0 + kk]);
    }
    __syncthreads();

    const int i0 = (t >> 4) * 4;
    const int jc = t & 15;
    float acc[4][4];
#pragma unroll
    for (int a = 0; a < 4; a++)
#pragma unroll
        for (int b = 0; b < 4; b++) acc[a][b] = 0.f;

    for (int kk = 0; kk < 64; kk++) {
        float qa[4], kb[4];
#pragma unroll
        for (int a = 0; a < 4; a++) qa[a] = Qs[(i0 + a) * 65 + kk];
#pragma unroll
        for (int b = 0; b < 4; b++) kb[b] = Ks[(jc + 16 * b) * 65 + kk];
#pragma unroll
        for (int a = 0; a < 4; a++)
#pragma unroll
            for (int b = 0; b < 4; b++) acc[a][b] += qa[a] * kb[b];
    }

#pragma unroll
    for (int a = 0; a < 4; a++) {
#pragma unroll
        for (int b = 0; b < 4; b++) {
            int i = i0 + a, j = jc + 16 * b;
            float val = acc[a][b] * 0.125f;
            if (has_prev) val += scores[sb + i * 64 + j];
            scores[sb + i * 64 + j] = val;
            Ss[i * 65 + j] = val;
        }
    }
    __syncthreads();

    const int w = t >> 5, lane = t & 31;
#pragma unroll
    for (int p = 0; p < 8; p++) {
        int r = w * 8 + p;
        float v0 = Ss[r * 65 + lane], v1 = Ss[r * 65 + lane + 32];
        float mx = fmaxf(v0, v1);
#pragma unroll
        for (int off = 16; off > 0; off >>= 1)
            mx = fmaxf(mx, __shfl_xor_sync(0xffffffffu, mx, off));
        float e0 = __expf(v0 - mx), e1 = __expf(v1 - mx);
        float sumv = e0 + e1;
#pragma unroll
        for (int off = 16; off > 0; off >>= 1)
            sumv += __shfl_xor_sync(0xffffffffu, sumv, off);
        float inv = 1.0f / sumv;
        e0 *= inv; e1 *= inv;
        Ss[r * 65 + lane] = e0;
        Ss[r * 65 + lane + 32] = e1;
        if (attn_out) {
            attn_out[sb + r * 64 + lane] = e0;
            attn_out[sb + r * 64 + lane + 32] = e1;
        }
    }
    __syncthreads();

#pragma unroll
    for (int s = 0; s < 16; s++) {
        int e = t + 256 * s;
        int i = e >> 6, kk = e & 63;
        Ks[i * 65 + kk] = __half2float(QKV[(size_t)(row0 + i) * QKVN + 2 * DM + c0 + kk]);
    }
    __syncthreads();

    float acc2[4][4];
#pragma unroll
    for (int a = 0; a < 4; a++)
#pragma unroll
        for (int b = 0; b < 4; b++) acc2[a][b] = 0.f;

    for (int j = 0; j < 64; j++) {
        float sa[4], vb[4];
#pragma unroll
        for (int a = 0; a < 4; a++) sa[a] = Ss[(i0 + a) * 65 + j];
#pragma unroll
        for (int b = 0; b < 4; b++) vb[b] = Ks[j * 65 + jc + 16 * b];
#pragma unroll
        for (int a = 0; a < 4; a++)
#pragma unroll
            for (int b = 0; b < 4; b++) acc2[a][b] += sa[a] * vb[b];
    }

#pragma unroll
    for (int a = 0; a < 4; a++)
#pragma unroll
        for (int b = 0; b < 4; b++)
            O[(size_t)(row0 + i0 + a) * DM + c0 + jc + 16 * b] = __float2half(acc2[a][b]);
}

// ---------------------------------------------------------------------------
// BatchNorm finalize
// ---------------------------------------------------------------------------
__global__ void zero_stats_kernel(float* stats)
{
    int idx = blockIdx.x * 256 + threadIdx.x;
    if (idx < 2 * DM) stats[idx] = 0.f;
}

__global__ __launch_bounds__(256) void bn_norm_kernel(
    float* __restrict__ u, __half* __restrict__ uh, const float* __restrict__ stats,
    const float* __restrict__ g, const float* __restrict__ be)
{
    int idx = blockIdx.x * 256 + threadIdx.x;
    int c = idx % DM;
    const float invM = 1.0f / (float)MROWS;
    float mean = stats[c] * invM;
    float var = stats[DM + c] * invM - mean * mean;
    float iv = rsqrtf(var + 1e-5f);
    float val = (u[idx] - mean) * iv * g[c] + be[c];
    u[idx] = val;
    uh[idx] = __float2half(val);
}

// ---------------------------------------------------------------------------
// Misc remap / transposes
// ---------------------------------------------------------------------------
__global__ __launch_bounds__(256) void remap_embed_kernel(
    const float* __restrict__ h, const float* __restrict__ Wpos,
    float* __restrict__ u, __half* __restrict__ uh)
{
    int idx = blockIdx.x * 256 + threadIdx.x;
    int ru = idx / DM, d = idx % DM;
    int bv = ru >> 6, n = ru & 63;
    int b = bv / 7, v = bv % 7;
    int rh = (b * 64 + n) * 7 + v;
    float val = h[(size_t)rh * DM + d] + Wpos[n * DM + d];
    u[idx] = val;
    uh[idx] = __float2half(val);
}

__global__ void transpose_h_kernel(const float* __restrict__ h, float* __restrict__ out)
{
    __shared__ float tile[32][33];
    int bv = blockIdx.z, b = bv / 7, v = bv % 7;
    int d0 = blockIdx.x * 32, n0 = blockIdx.y * 32;
#pragma unroll
    for (int i = 0; i < 32; i += 8) {
        int n = n0 + threadIdx.y + i;
        int d = d0 + threadIdx.x;
        tile[threadIdx.y + i][threadIdx.x] = h[((size_t)(b * 64 + n) * 7 + v) * DM + d];
    }
    __syncthreads();
#pragma unroll
    for (int i = 0; i < 32; i += 8) {
        int d = d0 + threadIdx.y + i;
        int n = n0 + threadIdx.x;
        out[((size_t)bv * DM + d) * LSEQ + n] = tile[threadIdx.x][threadIdx.y + i];
    }
}

// transpose_z with final BN2 applied inline (channel is constant per thread in
// the load phase: d = d0 + threadIdx.x)
__global__ void transpose_z_bn_kernel(
    const float* __restrict__ u, const float* __restrict__ stats,
    const float* __restrict__ g, const float* __restrict__ be,
    float* __restrict__ out)
{
    __shared__ float tile[32][33];
    int bv = blockIdx.z;
    int d0 = blockIdx.x * 32, n0 = blockIdx.y * 32;
    int d = d0 + threadIdx.x;
    const float invM = 1.0f / (float)MROWS;
    float mean = stats[d] * invM;
    float var = stats[DM + d] * invM - mean * mean;
    float scl = rsqrtf(var + 1e-5f) * g[d];
    float off = be[d] - mean * scl;
#pragma unroll
    for (int i = 0; i < 32; i += 8) {
        int n = n0 + threadIdx.y + i;
        tile[threadIdx.y + i][threadIdx.x] =
            u[(size_t)(bv * 64 + n) * DM + d] * scl + off;
    }
    __syncthreads();
#pragma unroll
    for (int i = 0; i < 32; i += 8) {
        int dd = d0 + threadIdx.y + i;
        int n = n0 + threadIdx.x;
        out[((size_t)bv * DM + dd) * LSEQ + n] = tile[threadIdx.x][threadIdx.y + i];
    }
}

// ---------------------------------------------------------------------------

extern "C" void kernel_launch(void* const* d_in, const int* in_sizes, int n_in,
                              void* d_out, int out_size)
{
    const float* x    = (const float*)d_in[0];
    const float* Wp   = (const float*)d_in[1];
    const float* bp   = (const float*)d_in[2];
    const float* Wpos = (const float*)d_in[3];
    const float* Wq   = (const float*)d_in[4];
    const float* bq   = (const float*)d_in[5];
    const float* Wk   = (const float*)d_in[6];
    const float* bk   = (const float*)d_in[7];
    const float* Wv   = (const float*)d_in[8];
    const float* bv_  = (const float*)d_in[9];
    const float* Wo   = (const float*)d_in[10];
    const float* bo   = (const float*)d_in[11];
    const float* g1   = (const float*)d_in[12];
    const float* be1  = (const float*)d_in[13];
    const float* W1   = (const float*)d_in[14];
    const float* b1   = (const float*)d_in[15];
    const float* W2   = (const float*)d_in[16];
    const float* b2   = (const float*)d_in[17];
    const float* g2   = (const float*)d_in[18];
    const float* be2  = (const float*)d_in[19];

    float* out      = (float*)d_out;
    float* out_z    = out;
    float* out_h    = out + OUTSZ;
    float* out_attn = out + 2 * (size_t)OUTSZ;

    float *u, *t, *sc, *st, *bqkv;
    __half *uh, *qkvh, *oh, *ffh, *wqkvt, *wot, *w1t, *w2t;
    cudaGetSymbolAddress((void**)&u,  g_u);
    cudaGetSymbolAddress((void**)&uh, g_uh);
    cudaGetSymbolAddress((void**)&qkvh, g_qkvh);
    cudaGetSymbolAddress((void**)&oh, g_oh);
    cudaGetSymbolAddress((void**)&t,  g_t);
    cudaGetSymbolAddress((void**)&ffh, g_ffh);
    cudaGetSymbolAddress((void**)&sc, g_scores);
    cudaGetSymbolAddress((void**)&st, g_stats);
    cudaGetSymbolAddress((void**)&bqkv, g_bqkv);
    cudaGetSymbolAddress((void**)&wqkvt, g_wqkvt);
    cudaGetSymbolAddress((void**)&wot, g_wot);
    cudaGetSymbolAddress((void**)&w1t, g_w1t);
    cudaGetSymbolAddress((void**)&w2t, g_w2t);

    cudaFuncSetAttribute(attn_kernel, cudaFuncAttributeMaxDynamicSharedMemorySize, 49920);
    cudaFuncSetAttribute(hgemm<0, 0, 1, 0>, cudaFuncAttributeMaxDynamicSharedMemorySize, HG_SMEM);
    cudaFuncSetAttribute(hgemm<0, 0, 0, 1>, cudaFuncAttributeMaxDynamicSharedMemorySize, HG_SMEM);
    cudaFuncSetAttribute(hgemm<1, 0, 1, 0>, cudaFuncAttributeMaxDynamicSharedMemorySize, HG_SMEM);

    const dim3 blk(256);
    const int elemBlocks = (MROWS * DM) / 256;
    const dim3 tgrid(24, 2, BH);
    const dim3 tblk32(32, 8);
    const dim3 gQKV(QKVN / 128, MROWS / 128);  // (18, 224)
    const dim3 gD(DM / 128, MROWS / 128);      // (6, 224)
    const dim3 gF(DF / 128, MROWS / 128);      // (24, 224)
    const dim3 gqkvW(24, 24, 4);
    const dim3 gdd(DM / 32, DM / 32);
    const dim3 g1d(DF / 32, DM / 32);
    const dim3 g2d(DM / 32, DF / 32);

    // launches 0-3: put the layer-0 QKV hgemm at index 3 (ncu captures #3)
    qkv_wtrans_kernel<<<gqkvW, tblk32>>>(Wq, Wk, Wv, bq, bk, bv_, wqkvt, bqkv);   // 0
    gemm_kernel<<<dim3(DM / 128, MROWS / 128), blk>>>(x, Wp, bp, t, MROWS, DM, 16); // 1
    remap_embed_kernel<<<elemBlocks, blk>>>(t, Wpos, u, uh);                       // 2
    hgemm<0, 0, 1, 0><<<gQKV, blk, HG_SMEM>>>(uh, wqkvt, bqkv,
                                              nullptr, qkvh, nullptr, nullptr, QKVN, DM); // 3

    transpose_h_kernel<<<tgrid, tblk32>>>(t, out_h);
    for (int l = 1; l < 3; l++)
        qkv_wtrans_kernel<<<gqkvW, tblk32>>>(
            Wq + (size_t)l * DM * DM, Wk + (size_t)l * DM * DM, Wv + (size_t)l * DM * DM,
            bq + l * DM, bk + l * DM, bv_ + l * DM,
            wqkvt + (size_t)l * QKVN * DM, bqkv + l * QKVN);
    for (int l = 0; l < 3; l++) {
        wtrans_kernel<<<gdd, tblk32>>>(Wo + (size_t)l * DM * DM, wot + (size_t)l * DM * DM, DM, DM);
        wtrans_kernel<<<g1d, tblk32>>>(W1 + (size_t)l * DM * DF, w1t + (size_t)l * DM * DF, DM, DF);
        wtrans_kernel<<<g2d, tblk32>>>(W2 + (size_t)l * DF * DM, w2t + (size_t)l * DF * DM, DF, DM);
    }

    for (int l = 0; l < 3; l++) {
        if (l > 0)
            hgemm<0, 0, 1, 0><<<gQKV, blk, HG_SMEM>>>(
                uh, wqkvt + (size_t)l * QKVN * DM, bqkv + l * QKVN,
                nullptr, qkvh, nullptr, nullptr, QKVN, DM);

        attn_kernel<<<BH * NHEAD, 256, 49920>>>(
            qkvh, sc, oh, (l == 2) ? out_attn : nullptr, (l > 0) ? 1 : 0);

        zero_stats_kernel<<<6, 256>>>(st);
        hgemm<0, 0, 0, 1><<<gD, blk, HG_SMEM>>>(oh, wot + (size_t)l * DM * DM, bo + l * DM,
                                                nullptr, nullptr, u, st, DM, DM);
        bn_norm_kernel<<<elemBlocks, blk>>>(u, uh, st, g1 + l * DM, be1 + l * DM);

        hgemm<1, 0, 1, 0><<<gF, blk, HG_SMEM>>>(uh, w1t + (size_t)l * DM * DF, b1 + l * DF,
                                                nullptr, ffh, nullptr, nullptr, DF, DM);
        zero_stats_kernel<<<6, 256>>>(st);
        hgemm<0, 0, 0, 1><<<gD, blk, HG_SMEM>>>(ffh, w2t + (size_t)l * DF * DM, b2 + l * DM,
                                                nullptr, nullptr, u, st, DM, DF);
        if (l < 2)
            bn_norm_kernel<<<elemBlocks, blk>>>(u, uh, st, g2 + l * DM, be2 + l * DM);
    }

    // final BN2 folded into output transpose
    transpose_z_bn_kernel<<<tgrid, tblk32>>>(u, st, g2 + 2 * DM, be2 + 2 * DM, out_z);
}

// round 12
// speedup vs baseline: 1.3420x; 1.0734x over previous
#include <cuda_runtime.h>
#include <cuda_fp16.h>
#include <math.h>
#include <stdint.h>

// ---------------------------------------------------------------------------
// RockTS encoder. R12 (= R10 with pack_half2 fix): tensor-core attention
// (m16n8k16 + ldmatrix.trans for V, scores in registers, C->A frag remap for
// P@V). Rest = R9 config.
// ---------------------------------------------------------------------------

#define MROWS 28672
#define DM    768
#define DF    3072
#define QKVN  2304
#define LSEQ  64
#define BH    448
#define NHEAD 12
#define OUTSZ 22020096

__device__ float  g_u[MROWS * DM];
__device__ __half g_uh[MROWS * DM];
__device__ __half g_qkvh[MROWS * QKVN];
__device__ __half g_oh[MROWS * DM];
__device__ float  g_t[MROWS * DM];
__device__ __half g_ffh[MROWS * DF];
__device__ float  g_scores[BH * NHEAD * LSEQ * LSEQ];
__device__ float  g_stats[2 * DM];
__device__ __half g_wqkvt[3 * QKVN * DM];
__device__ float  g_bqkv[3 * QKVN];
__device__ __half g_wot[3 * DM * DM];
__device__ __half g_w1t[3 * DM * DF];
__device__ __half g_w2t[3 * DF * DM];

// pack two floats into a half2 register (lo, hi)
__device__ __forceinline__ uint32_t pack_half2(float lo, float hi) {
    uint32_t r;
    asm("cvt.rn.f16x2.f32 %0, %1, %2;" : "=r"(r) : "f"(hi), "f"(lo));
    return r;
}

// ---------------------------------------------------------------------------
// fp16 MMA GEMM (R9): BM=BN=128, BK=32, 4-stage cp.async, 1 sync/iter.
// ---------------------------------------------------------------------------
#define SROWH 40
#define STAGE_BYTES (128 * SROWH * 2)
#define HG_SMEM (4 * 2 * STAGE_BYTES)

__device__ __forceinline__ void cpasync16u(uint32_t sa, const void* gp) {
    asm volatile("cp.async.cg.shared.global [%0], [%1], 16;" :: "r"(sa), "l"(gp));
}

template<int GELU_EPI, int WRITE_F, int WRITE_H, int RESID>
__global__ __launch_bounds__(256, 2) void hgemm(
    const __half* __restrict__ A, const __half* __restrict__ Bt,
    const float* __restrict__ bias, float* __restrict__ Cf,
    __half* __restrict__ Ch, float* __restrict__ U, float* __restrict__ stats,
    int N, int K)
{
    extern __shared__ char dsm[];
    const uint32_t sbase = (uint32_t)__cvta_generic_to_shared(dsm);
    const int tid  = threadIdx.x;
    const int wid  = tid >> 5, lane = tid & 31;
    const int g    = lane >> 2, tig = lane & 3;
    const int wm   = (wid & 1) * 64;
    const int wn   = (wid >> 1) * 32;
    const int m0   = blockIdx.y * 128, n0 = blockIdx.x * 128;
    const int NK   = K >> 5;

    const int arow  = lane & 15;
    const int akoff = (lane & 16) >> 1;
    const int nrow  = ((lane & 16) >> 1) + (lane & 7);
    const int bkoff = lane & 8;
    const uint32_t aOff = sbase + ((wm + arow) * SROWH + akoff) * 2;
    const uint32_t bOff = sbase + STAGE_BYTES + ((wn + nrow) * SROWH + bkoff) * 2;

    float acc[16][4];
#pragma unroll
    for (int i = 0; i < 16; i++)
#pragma unroll
        for (int j = 0; j < 4; j++) acc[i][j] = 0.f;

    auto load_stage = [&](int stg, int it) {
        const __half* Ab = A + (size_t)m0 * K + it * 32;
        const __half* Bb = Bt + (size_t)n0 * K + it * 32;
        uint32_t dA = sbase + stg * (2 * STAGE_BYTES);
        uint32_t dB = dA + STAGE_BYTES;
#pragma unroll
        for (int r = 0; r < 2; r++) {
            int c = tid + 256 * r;
            int row = c >> 2, cj = c & 3;
            cpasync16u(dA + (row * SROWH + cj * 8) * 2, Ab + (size_t)row * K + cj * 8);
            cpasync16u(dB + (row * SROWH + cj * 8) * 2, Bb + (size_t)row * K + cj * 8);
        }
        asm volatile("cp.async.commit_group;");
    };

    load_stage(0, 0);
    if (NK > 1) load_stage(1, 1);
    if (NK > 2) load_stage(2, 2);

    for (int it = 0; it < NK; it++) {
        const int s = it & 3;
        if (it + 2 < NK)      asm volatile("cp.async.wait_group 2;");
        else if (it + 1 < NK) asm volatile("cp.async.wait_group 1;");
        else                  asm volatile("cp.async.wait_group 0;");
        __syncthreads();
        if (it + 3 < NK) load_stage((it + 3) & 3, it + 3);

        const uint32_t aS = aOff + s * (2 * STAGE_BYTES);
        const uint32_t bS = bOff + s * (2 * STAGE_BYTES);
#pragma unroll
        for (int ks = 0; ks < 2; ks++) {
            uint32_t a[4][4], b[4][2];
#pragma unroll
            for (int mt = 0; mt < 4; mt++) {
                uint32_t ad = aS + mt * (16 * SROWH * 2) + ks * 32;
                asm volatile("ldmatrix.sync.aligned.m8n8.x4.shared.b16 {%0,%1,%2,%3}, [%4];"
                             : "=r"(a[mt][0]), "=r"(a[mt][1]), "=r"(a[mt][2]), "=r"(a[mt][3])
                             : "r"(ad));
            }
#pragma unroll
            for (int p = 0; p < 2; p++) {
                uint32_t bd = bS + p * (16 * SROWH * 2) + ks * 32;
                asm volatile("ldmatrix.sync.aligned.m8n8.x4.shared.b16 {%0,%1,%2,%3}, [%4];"
                             : "=r"(b[2 * p][0]), "=r"(b[2 * p][1]),
                               "=r"(b[2 * p + 1][0]), "=r"(b[2 * p + 1][1])
                             : "r"(bd));
            }
#pragma unroll
            for (int mt = 0; mt < 4; mt++)
#pragma unroll
                for (int nt = 0; nt < 4; nt++) {
                    float* c = acc[mt * 4 + nt];
                    asm volatile(
                        "mma.sync.aligned.m16n8k16.row.col.f32.f16.f16.f32 "
                        "{%0,%1,%2,%3}, {%4,%5,%6,%7}, {%8,%9}, {%0,%1,%2,%3};"
                        : "+f"(c[0]), "+f"(c[1]), "+f"(c[2]), "+f"(c[3])
                        : "r"(a[mt][0]), "r"(a[mt][1]), "r"(a[mt][2]), "r"(a[mt][3]),
                          "r"(b[nt][0]), "r"(b[nt][1]));
                }
        }
    }

    float cs[8], cq[8];
    if (RESID) {
#pragma unroll
        for (int i = 0; i < 8; i++) { cs[i] = 0.f; cq[i] = 0.f; }
    }
#pragma unroll
    for (int mt = 0; mt < 4; mt++) {
#pragma unroll
        for (int nt = 0; nt < 4; nt++) {
            const float* c = acc[mt * 4 + nt];
            int col = n0 + wn + nt * 8 + 2 * tig;
            float b0 = bias[col], b1 = bias[col + 1];
            int r0 = m0 + wm + mt * 16 + g;
            float2 v0, v1;
            v0.x = c[0] + b0; v0.y = c[1] + b1;
            v1.x = c[2] + b0; v1.y = c[3] + b1;
            if (GELU_EPI) {
                v0.x = 0.5f * v0.x * (1.0f + erff(v0.x * 0.70710678118654752f));
                v0.y = 0.5f * v0.y * (1.0f + erff(v0.y * 0.70710678118654752f));
                v1.x = 0.5f * v1.x * (1.0f + erff(v1.x * 0.70710678118654752f));
                v1.y = 0.5f * v1.y * (1.0f + erff(v1.y * 0.70710678118654752f));
            }
            if (RESID) {
                float2 u0 = *(float2*)&U[(size_t)r0 * N + col];
                float2 u1 = *(float2*)&U[(size_t)(r0 + 8) * N + col];
                v0.x += u0.x; v0.y += u0.y;
                v1.x += u1.x; v1.y += u1.y;
                *(float2*)&U[(size_t)r0 * N + col] = v0;
                *(float2*)&U[(size_t)(r0 + 8) * N + col] = v1;
                cs[nt * 2 + 0] += v0.x + v1.x;
                cs[nt * 2 + 1] += v0.y + v1.y;
                cq[nt * 2 + 0] += v0.x * v0.x + v1.x * v1.x;
                cq[nt * 2 + 1] += v0.y * v0.y + v1.y * v1.y;
            }
            if (WRITE_F) {
                *(float2*)&Cf[(size_t)r0 * N + col] = v0;
                *(float2*)&Cf[(size_t)(r0 + 8) * N + col] = v1;
            }
            if (WRITE_H) {
                __half2 h0, h1;
                h0.x = __float2half(v0.x); h0.y = __float2half(v0.y);
                h1.x = __float2half(v1.x); h1.y = __float2half(v1.y);
                *(__half2*)&Ch[(size_t)r0 * N + col] = h0;
                *(__half2*)&Ch[(size_t)(r0 + 8) * N + col] = h1;
            }
        }
    }
    if (RESID) {
#pragma unroll
        for (int i = 0; i < 8; i++) {
            cs[i] += __shfl_down_sync(0xffffffffu, cs[i], 16);
            cs[i] += __shfl_down_sync(0xffffffffu, cs[i], 8);
            cs[i] += __shfl_down_sync(0xffffffffu, cs[i], 4);
            cq[i] += __shfl_down_sync(0xffffffffu, cq[i], 16);
            cq[i] += __shfl_down_sync(0xffffffffu, cq[i], 8);
            cq[i] += __shfl_down_sync(0xffffffffu, cq[i], 4);
        }
        if (lane < 4) {
#pragma unroll
            for (int nt = 0; nt < 4; nt++) {
                int col = n0 + wn + nt * 8 + 2 * tig;
                atomicAdd(&stats[col],     cs[nt * 2 + 0]);
                atomicAdd(&stats[col + 1], cs[nt * 2 + 1]);
                atomicAdd(&stats[DM + col],     cq[nt * 2 + 0]);
                atomicAdd(&stats[DM + col + 1], cq[nt * 2 + 1]);
            }
        }
    }
}

// ---------------------------------------------------------------------------
// fp32 SGEMM (patch embed, K=16)
// ---------------------------------------------------------------------------
__global__ __launch_bounds__(256, 2) void gemm_kernel(
    const float* __restrict__ A, const float* __restrict__ B,
    const float* __restrict__ bias, float* __restrict__ C,
    int Mdim, int Ndim, int Kdim)
{
    __shared__ float As[16][128];
    __shared__ float Bs[16][132];
    const int tid = threadIdx.x;
    const int tx = tid & 15, ty = tid >> 4;
    const int m0 = blockIdx.y * 128, n0 = blockIdx.x * 128;
    float acc[8][8];
#pragma unroll
    for (int i = 0; i < 8; i++)
#pragma unroll
        for (int j = 0; j < 8; j++) acc[i][j] = 0.f;
    for (int k0 = 0; k0 < Kdim; k0 += 16) {
#pragma unroll
        for (int s = 0; s < 2; s++) {
            int f4 = tid + 256 * s;
            int row = f4 >> 2, kq = (f4 & 3) * 4;
            float4 av = *(const float4*)&A[(size_t)(m0 + row) * Kdim + k0 + kq];
            As[kq + 0][row] = av.x; As[kq + 1][row] = av.y;
            As[kq + 2][row] = av.z; As[kq + 3][row] = av.w;
        }
#pragma unroll
        for (int s = 0; s < 2; s++) {
            int f4 = tid + 256 * s;
            int row = f4 >> 5, nq = (f4 & 31) * 4;
            *(float4*)&Bs[row][nq] = *(const float4*)&B[(size_t)(k0 + row) * Ndim + n0 + nq];
        }
        __syncthreads();
#pragma unroll
        for (int k = 0; k < 16; k++) {
            float a[8], b[8];
            *(float4*)&a[0] = *(const float4*)&As[k][ty * 8];
            *(float4*)&a[4] = *(const float4*)&As[k][ty * 8 + 4];
            *(float4*)&b[0] = *(const float4*)&Bs[k][tx * 8];
            *(float4*)&b[4] = *(const float4*)&Bs[k][tx * 8 + 4];
#pragma unroll
            for (int i = 0; i < 8; i++)
#pragma unroll
                for (int j = 0; j < 8; j++) acc[i][j] += a[i] * b[j];
        }
        __syncthreads();
    }
#pragma unroll
    for (int i = 0; i < 8; i++) {
        int row = m0 + ty * 8 + i;
#pragma unroll
        for (int j = 0; j < 8; j++) {
            int col = n0 + tx * 8 + j;
            C[(size_t)row * Ndim + col] = acc[i][j] + bias[col];
        }
    }
}

// ---------------------------------------------------------------------------
// QKV weight transpose + bias concat
// ---------------------------------------------------------------------------
__global__ void qkv_wtrans_kernel(
    const float* __restrict__ Wq, const float* __restrict__ Wk,
    const float* __restrict__ Wv, const float* __restrict__ bq,
    const float* __restrict__ bk, const float* __restrict__ bv,
    __half* __restrict__ wout, float* __restrict__ bout)
{
    int z = blockIdx.z;
    if (z == 3) {
        int idx = (blockIdx.y * gridDim.x + blockIdx.x) * 256 +
                  threadIdx.y * 32 + threadIdx.x;
        if (idx < QKVN) {
            int sec = idx / DM, cc = idx % DM;
            const float* src = (sec == 0) ? bq : (sec == 1) ? bk : bv;
            bout[idx] = src[cc];
        }
        return;
    }
    const float* W = (z == 0) ? Wq : (z == 1) ? Wk : Wv;
    __shared__ float tl[32][33];
    int c0 = blockIdx.x * 32, r0 = blockIdx.y * 32;
#pragma unroll
    for (int i = 0; i < 32; i += 8)
        tl[threadIdx.y + i][threadIdx.x] = W[(size_t)(r0 + threadIdx.y + i) * DM + c0 + threadIdx.x];
    __syncthreads();
#pragma unroll
    for (int i = 0; i < 32; i += 8)
        wout[(size_t)(z * DM + c0 + threadIdx.y + i) * DM + r0 + threadIdx.x] =
            __float2half(tl[threadIdx.x][threadIdx.y + i]);
}

__global__ void wtrans_kernel(const float* __restrict__ in, __half* __restrict__ out,
                              int R, int Ccols)
{
    __shared__ float tl[32][33];
    int c0 = blockIdx.x * 32, r0 = blockIdx.y * 32;
#pragma unroll
    for (int i = 0; i < 32; i += 8)
        tl[threadIdx.y + i][threadIdx.x] = in[(size_t)(r0 + threadIdx.y + i) * Ccols + c0 + threadIdx.x];
    __syncthreads();
#pragma unroll
    for (int i = 0; i < 32; i += 8)
        out[(size_t)(c0 + threadIdx.y + i) * R + r0 + threadIdx.x] =
            __float2half(tl[threadIdx.x][threadIdx.y + i]);
}

// ---------------------------------------------------------------------------
// Tensor-core attention per (batch, head). 128 threads = 4 warps, each warp
// owns 16 query rows. QK^T and P@V on m16n8k16; scores stay in registers.
// smem rows padded to 72 halfs (bank-conflict-free ldmatrix).
// ---------------------------------------------------------------------------
#define AROW 72

__global__ __launch_bounds__(128) void attn_mma_kernel(
    const __half* __restrict__ QKV, float* __restrict__ scores,
    __half* __restrict__ O, float* __restrict__ attn_out, int has_prev)
{
    __shared__ __align__(16) __half Qs[64 * AROW];
    __shared__ __align__(16) __half Ks[64 * AROW];
    __shared__ __align__(16) __half Vs[64 * AROW];

    const int bh = blockIdx.x;
    const int bv = bh / NHEAD, h = bh % NHEAD;
    const int row0 = bv * LSEQ, c0 = h * 64;
    const int tid = threadIdx.x;
    const int wid = tid >> 5, lane = tid & 31;
    const int g = lane >> 2, tig = lane & 3;
    const int wm = wid * 16;
    const size_t sb = (size_t)bh * 4096;

    for (int e = tid; e < 512; e += 128) {
        int r = e >> 3, cj = e & 7;
        const __half* base = QKV + (size_t)(row0 + r) * QKVN + c0 + cj * 8;
        *(uint4*)&Qs[r * AROW + cj * 8] = *(const uint4*)(base);
        *(uint4*)&Ks[r * AROW + cj * 8] = *(const uint4*)(base + DM);
        *(uint4*)&Vs[r * AROW + cj * 8] = *(const uint4*)(base + 2 * DM);
    }
    __syncthreads();

    const uint32_t qsb = (uint32_t)__cvta_generic_to_shared(Qs);
    const uint32_t ksb = (uint32_t)__cvta_generic_to_shared(Ks);
    const uint32_t vsb = (uint32_t)__cvta_generic_to_shared(Vs);

    const int arow  = lane & 15;
    const int akoff = (lane & 16) >> 1;
    const int nrow  = ((lane & 16) >> 1) + (lane & 7);
    const int bkoff = lane & 8;

    // ---- QK^T ----
    float sc[8][4];
#pragma unroll
    for (int i = 0; i < 8; i++)
#pragma unroll
        for (int j = 0; j < 4; j++) sc[i][j] = 0.f;

#pragma unroll
    for (int ks = 0; ks < 4; ks++) {
        uint32_t a[4];
        uint32_t ad = qsb + ((wm + arow) * AROW + 16 * ks + akoff) * 2;
        asm volatile("ldmatrix.sync.aligned.m8n8.x4.shared.b16 {%0,%1,%2,%3}, [%4];"
                     : "=r"(a[0]), "=r"(a[1]), "=r"(a[2]), "=r"(a[3]) : "r"(ad));
#pragma unroll
        for (int p = 0; p < 4; p++) {
            uint32_t b[4];
            uint32_t bd = ksb + ((16 * p + nrow) * AROW + 16 * ks + bkoff) * 2;
            asm volatile("ldmatrix.sync.aligned.m8n8.x4.shared.b16 {%0,%1,%2,%3}, [%4];"
                         : "=r"(b[0]), "=r"(b[1]), "=r"(b[2]), "=r"(b[3]) : "r"(bd));
#pragma unroll
            for (int q = 0; q < 2; q++) {
                float* c = sc[2 * p + q];
                asm volatile(
                    "mma.sync.aligned.m16n8k16.row.col.f32.f16.f16.f32 "
                    "{%0,%1,%2,%3}, {%4,%5,%6,%7}, {%8,%9}, {%0,%1,%2,%3};"
                    : "+f"(c[0]), "+f"(c[1]), "+f"(c[2]), "+f"(c[3])
                    : "r"(a[0]), "r"(a[1]), "r"(a[2]), "r"(a[3]),
                      "r"(b[2 * q]), "r"(b[2 * q + 1]));
            }
        }
    }

    // ---- scale + prev + raw-score store, register softmax ----
    const int ri0 = wm + g, ri1 = wm + g + 8;
    float m0 = -1e30f, m1 = -1e30f;
#pragma unroll
    for (int nt = 0; nt < 8; nt++) {
        float v0 = sc[nt][0] * 0.125f, v1 = sc[nt][1] * 0.125f;
        float v2 = sc[nt][2] * 0.125f, v3 = sc[nt][3] * 0.125f;
        int coff = 8 * nt + 2 * tig;
        if (has_prev) {
            float2 p0 = *(float2*)&scores[sb + ri0 * 64 + coff];
            float2 p1 = *(float2*)&scores[sb + ri1 * 64 + coff];
            v0 += p0.x; v1 += p0.y; v2 += p1.x; v3 += p1.y;
        }
        float2 s0 = { v0, v1 }, s1 = { v2, v3 };
        *(float2*)&scores[sb + ri0 * 64 + coff] = s0;
        *(float2*)&scores[sb + ri1 * 64 + coff] = s1;
        sc[nt][0] = v0; sc[nt][1] = v1; sc[nt][2] = v2; sc[nt][3] = v3;
        m0 = fmaxf(m0, fmaxf(v0, v1));
        m1 = fmaxf(m1, fmaxf(v2, v3));
    }
    m0 = fmaxf(m0, __shfl_xor_sync(0xffffffffu, m0, 1));
    m0 = fmaxf(m0, __shfl_xor_sync(0xffffffffu, m0, 2));
    m1 = fmaxf(m1, __shfl_xor_sync(0xffffffffu, m1, 1));
    m1 = fmaxf(m1, __shfl_xor_sync(0xffffffffu, m1, 2));

    float s0 = 0.f, s1 = 0.f;
#pragma unroll
    for (int nt = 0; nt < 8; nt++) {
        sc[nt][0] = __expf(sc[nt][0] - m0);
        sc[nt][1] = __expf(sc[nt][1] - m0);
        sc[nt][2] = __expf(sc[nt][2] - m1);
        sc[nt][3] = __expf(sc[nt][3] - m1);
        s0 += sc[nt][0] + sc[nt][1];
        s1 += sc[nt][2] + sc[nt][3];
    }
    s0 += __shfl_xor_sync(0xffffffffu, s0, 1);
    s0 += __shfl_xor_sync(0xffffffffu, s0, 2);
    s1 += __shfl_xor_sync(0xffffffffu, s1, 1);
    s1 += __shfl_xor_sync(0xffffffffu, s1, 2);
    float inv0 = 1.0f / s0, inv1 = 1.0f / s1;

#pragma unroll
    for (int nt = 0; nt < 8; nt++) {
        sc[nt][0] *= inv0; sc[nt][1] *= inv0;
        sc[nt][2] *= inv1; sc[nt][3] *= inv1;
        if (attn_out) {
            int coff = 8 * nt + 2 * tig;
            float2 p0 = { sc[nt][0], sc[nt][1] };
            float2 p1 = { sc[nt][2], sc[nt][3] };
            *(float2*)&attn_out[sb + ri0 * 64 + coff] = p0;
            *(float2*)&attn_out[sb + ri1 * 64 + coff] = p1;
        }
    }

    // ---- P @ V ----
    float oacc[8][4];
#pragma unroll
    for (int i = 0; i < 8; i++)
#pragma unroll
        for (int j = 0; j < 4; j++) oacc[i][j] = 0.f;

    const int vrow = (lane & 7) + (lane & 8);
    const int vkoff = (lane & 16) >> 1;
#pragma unroll
    for (int jt = 0; jt < 4; jt++) {
        uint32_t a[4];
        a[0] = pack_half2(sc[2 * jt][0], sc[2 * jt][1]);
        a[1] = pack_half2(sc[2 * jt][2], sc[2 * jt][3]);
        a[2] = pack_half2(sc[2 * jt + 1][0], sc[2 * jt + 1][1]);
        a[3] = pack_half2(sc[2 * jt + 1][2], sc[2 * jt + 1][3]);
#pragma unroll
        for (int dp = 0; dp < 4; dp++) {
            uint32_t b[4];
            uint32_t bd = vsb + ((16 * jt + vrow) * AROW + 16 * dp + vkoff) * 2;
            asm volatile("ldmatrix.sync.aligned.m8n8.x4.trans.shared.b16 {%0,%1,%2,%3}, [%4];"
                         : "=r"(b[0]), "=r"(b[1]), "=r"(b[2]), "=r"(b[3]) : "r"(bd));
#pragma unroll
            for (int q = 0; q < 2; q++) {
                float* c = oacc[2 * dp + q];
                asm volatile(
                    "mma.sync.aligned.m16n8k16.row.col.f32.f16.f16.f32 "
                    "{%0,%1,%2,%3}, {%4,%5,%6,%7}, {%8,%9}, {%0,%1,%2,%3};"
                    : "+f"(c[0]), "+f"(c[1]), "+f"(c[2]), "+f"(c[3])
                    : "r"(a[0]), "r"(a[1]), "r"(a[2]), "r"(a[3]),
                      "r"(b[2 * q]), "r"(b[2 * q + 1]));
            }
        }
    }

#pragma unroll
    for (int nt = 0; nt < 8; nt++) {
        int col = c0 + 8 * nt + 2 * tig;
        __half2 h0, h1;
        h0.x = __float2half(oacc[nt][0]); h0.y = __float2half(oacc[nt][1]);
        h1.x = __float2half(oacc[nt][2]); h1.y = __float2half(oacc[nt][3]);
        *(__half2*)&O[(size_t)(row0 + ri0) * DM + col] = h0;
        *(__half2*)&O[(size_t)(row0 + ri1) * DM + col] = h1;
    }
}

// ---------------------------------------------------------------------------
// BatchNorm finalize
// ---------------------------------------------------------------------------
__global__ void zero_stats_kernel(float* stats)
{
    int idx = blockIdx.x * 256 + threadIdx.x;
    if (idx < 2 * DM) stats[idx] = 0.f;
}

__global__ __launch_bounds__(256) void bn_norm_kernel(
    float* __restrict__ u, __half* __restrict__ uh, const float* __restrict__ stats,
    const float* __restrict__ g, const float* __restrict__ be)
{
    int idx = blockIdx.x * 256 + threadIdx.x;
    int c = idx % DM;
    const float invM = 1.0f / (float)MROWS;
    float mean = stats[c] * invM;
    float var = stats[DM + c] * invM - mean * mean;
    float iv = rsqrtf(var + 1e-5f);
    float val = (u[idx] - mean) * iv * g[c] + be[c];
    u[idx] = val;
    uh[idx] = __float2half(val);
}

// ---------------------------------------------------------------------------
// Misc remap / transposes
// ---------------------------------------------------------------------------
__global__ __launch_bounds__(256) void remap_embed_kernel(
    const float* __restrict__ h, const float* __restrict__ Wpos,
    float* __restrict__ u, __half* __restrict__ uh)
{
    int idx = blockIdx.x * 256 + threadIdx.x;
    int ru = idx / DM, d = idx % DM;
    int bv = ru >> 6, n = ru & 63;
    int b = bv / 7, v = bv % 7;
    int rh = (b * 64 + n) * 7 + v;
    float val = h[(size_t)rh * DM + d] + Wpos[n * DM + d];
    u[idx] = val;
    uh[idx] = __float2half(val);
}

__global__ void transpose_h_kernel(const float* __restrict__ h, float* __restrict__ out)
{
    __shared__ float tile[32][33];
    int bv = blockIdx.z, b = bv / 7, v = bv % 7;
    int d0 = blockIdx.x * 32, n0 = blockIdx.y * 32;
#pragma unroll
    for (int i = 0; i < 32; i += 8) {
        int n = n0 + threadIdx.y + i;
        int d = d0 + threadIdx.x;
        tile[threadIdx.y + i][threadIdx.x] = h[((size_t)(b * 64 + n) * 7 + v) * DM + d];
    }
    __syncthreads();
#pragma unroll
    for (int i = 0; i < 32; i += 8) {
        int d = d0 + threadIdx.y + i;
        int n = n0 + threadIdx.x;
        out[((size_t)bv * DM + d) * LSEQ + n] = tile[threadIdx.x][threadIdx.y + i];
    }
}

__global__ void transpose_z_bn_kernel(
    const float* __restrict__ u, const float* __restrict__ stats,
    const float* __restrict__ g, const float* __restrict__ be,
    float* __restrict__ out)
{
    __shared__ float tile[32][33];
    int bv = blockIdx.z;
    int d0 = blockIdx.x * 32, n0 = blockIdx.y * 32;
    int d = d0 + threadIdx.x;
    const float invM = 1.0f / (float)MROWS;
    float mean = stats[d] * invM;
    float var = stats[DM + d] * invM - mean * mean;
    float scl = rsqrtf(var + 1e-5f) * g[d];
    float off = be[d] - mean * scl;
#pragma unroll
    for (int i = 0; i < 32; i += 8) {
        int n = n0 + threadIdx.y + i;
        tile[threadIdx.y + i][threadIdx.x] =
            u[(size_t)(bv * 64 + n) * DM + d] * scl + off;
    }
    __syncthreads();
#pragma unroll
    for (int i = 0; i < 32; i += 8) {
        int dd = d0 + threadIdx.y + i;
        int n = n0 + threadIdx.x;
        out[((size_t)bv * DM + dd) * LSEQ + n] = tile[threadIdx.x][threadIdx.y + i];
    }
}

// ---------------------------------------------------------------------------

extern "C" void kernel_launch(void* const* d_in, const int* in_sizes, int n_in,
                              void* d_out, int out_size)
{
    const float* x    = (const float*)d_in[0];
    const float* Wp   = (const float*)d_in[1];
    const float* bp   = (const float*)d_in[2];
    const float* Wpos = (const float*)d_in[3];
    const float* Wq   = (const float*)d_in[4];
    const float* bq   = (const float*)d_in[5];
    const float* Wk   = (const float*)d_in[6];
    const float* bk   = (const float*)d_in[7];
    const float* Wv   = (const float*)d_in[8];
    const float* bv_  = (const float*)d_in[9];
    const float* Wo   = (const float*)d_in[10];
    const float* bo   = (const float*)d_in[11];
    const float* g1   = (const float*)d_in[12];
    const float* be1  = (const float*)d_in[13];
    const float* W1   = (const float*)d_in[14];
    const float* b1   = (const float*)d_in[15];
    const float* W2   = (const float*)d_in[16];
    const float* b2   = (const float*)d_in[17];
    const float* g2   = (const float*)d_in[18];
    const float* be2  = (const float*)d_in[19];

    float* out      = (float*)d_out;
    float* out_z    = out;
    float* out_h    = out + OUTSZ;
    float* out_attn = out + 2 * (size_t)OUTSZ;

    float *u, *t, *sc, *st, *bqkv;
    __half *uh, *qkvh, *oh, *ffh, *wqkvt, *wot, *w1t, *w2t;
    cudaGetSymbolAddress((void**)&u,  g_u);
    cudaGetSymbolAddress((void**)&uh, g_uh);
    cudaGetSymbolAddress((void**)&qkvh, g_qkvh);
    cudaGetSymbolAddress((void**)&oh, g_oh);
    cudaGetSymbolAddress((void**)&t,  g_t);
    cudaGetSymbolAddress((void**)&ffh, g_ffh);
    cudaGetSymbolAddress((void**)&sc, g_scores);
    cudaGetSymbolAddress((void**)&st, g_stats);
    cudaGetSymbolAddress((void**)&bqkv, g_bqkv);
    cudaGetSymbolAddress((void**)&wqkvt, g_wqkvt);
    cudaGetSymbolAddress((void**)&wot, g_wot);
    cudaGetSymbolAddress((void**)&w1t, g_w1t);
    cudaGetSymbolAddress((void**)&w2t, g_w2t);

    cudaFuncSetAttribute(hgemm<0, 0, 1, 0>, cudaFuncAttributeMaxDynamicSharedMemorySize, HG_SMEM);
    cudaFuncSetAttribute(hgemm<0, 0, 0, 1>, cudaFuncAttributeMaxDynamicSharedMemorySize, HG_SMEM);
    cudaFuncSetAttribute(hgemm<1, 0, 1, 0>, cudaFuncAttributeMaxDynamicSharedMemorySize, HG_SMEM);

    const dim3 blk(256);
    const int elemBlocks = (MROWS * DM) / 256;
    const dim3 tgrid(24, 2, BH);
    const dim3 tblk32(32, 8);
    const dim3 gQKV(QKVN / 128, MROWS / 128);
    const dim3 gD(DM / 128, MROWS / 128);
    const dim3 gF(DF / 128, MROWS / 128);
    const dim3 gqkvW(24, 24, 4);
    const dim3 gdd(DM / 32, DM / 32);
    const dim3 g1d(DF / 32, DM / 32);
    const dim3 g2d(DM / 32, DF / 32);

    qkv_wtrans_kernel<<<gqkvW, tblk32>>>(Wq, Wk, Wv, bq, bk, bv_, wqkvt, bqkv);   // 0
    gemm_kernel<<<dim3(DM / 128, MROWS / 128), blk>>>(x, Wp, bp, t, MROWS, DM, 16); // 1
    remap_embed_kernel<<<elemBlocks, blk>>>(t, Wpos, u, uh);                       // 2
    hgemm<0, 0, 1, 0><<<gQKV, blk, HG_SMEM>>>(uh, wqkvt, bqkv,
                                              nullptr, qkvh, nullptr, nullptr, QKVN, DM); // 3

    transpose_h_kernel<<<tgrid, tblk32>>>(t, out_h);
    for (int l = 1; l < 3; l++)
        qkv_wtrans_kernel<<<gqkvW, tblk32>>>(
            Wq + (size_t)l * DM * DM, Wk + (size_t)l * DM * DM, Wv + (size_t)l * DM * DM,
            bq + l * DM, bk + l * DM, bv_ + l * DM,
            wqkvt + (size_t)l * QKVN * DM, bqkv + l * QKVN);
    for (int l = 0; l < 3; l++) {
        wtrans_kernel<<<gdd, tblk32>>>(Wo + (size_t)l * DM * DM, wot + (size_t)l * DM * DM, DM, DM);
        wtrans_kernel<<<g1d, tblk32>>>(W1 + (size_t)l * DM * DF, w1t + (size_t)l * DM * DF, DM, DF);
        wtrans_kernel<<<g2d, tblk32>>>(W2 + (size_t)l * DF * DM, w2t + (size_t)l * DF * DM, DF, DM);
    }

    for (int l = 0; l < 3; l++) {
        if (l > 0)
            hgemm<0, 0, 1, 0><<<gQKV, blk, HG_SMEM>>>(
                uh, wqkvt + (size_t)l * QKVN * DM, bqkv + l * QKVN,
                nullptr, qkvh, nullptr, nullptr, QKVN, DM);

        attn_mma_kernel<<<BH * NHEAD, 128>>>(
            qkvh, sc, oh, (l == 2) ? out_attn : nullptr, (l > 0) ? 1 : 0);

        zero_stats_kernel<<<6, 256>>>(st);
        hgemm<0, 0, 0, 1><<<gD, blk, HG_SMEM>>>(oh, wot + (size_t)l * DM * DM, bo + l * DM,
                                                nullptr, nullptr, u, st, DM, DM);
        bn_norm_kernel<<<elemBlocks, blk>>>(u, uh, st, g1 + l * DM, be1 + l * DM);

        hgemm<1, 0, 1, 0><<<gF, blk, HG_SMEM>>>(uh, w1t + (size_t)l * DM * DF, b1 + l * DF,
                                                nullptr, ffh, nullptr, nullptr, DF, DM);
        zero_stats_kernel<<<6, 256>>>(st);
        hgemm<0, 0, 0, 1><<<gD, blk, HG_SMEM>>>(ffh, w2t + (size_t)l * DF * DM, b2 + l * DM,
                                                nullptr, nullptr, u, st, DM, DF);
        if (l < 2)
            bn_norm_kernel<<<elemBlocks, blk>>>(u, uh, st, g2 + l * DM, be2 + l * DM);
    }

    transpose_z_bn_kernel<<<tgrid, tblk32>>>(u, st, g2 + 2 * DM, be2 + 2 * DM, out_z);
}

// round 13
// speedup vs baseline: 1.4536x; 1.0832x over previous
#include <cuda_runtime.h>
#include <cuda_fp16.h>
#include <math.h>
#include <stdint.h>

// ---------------------------------------------------------------------------
// RockTS encoder. R13: hgemm BK=64, 3-stage, 1 sync/iter (halved barriers).
// Tensor-core attention + BN-fused epilogues as in R12.
// ---------------------------------------------------------------------------

#define MROWS 28672
#define DM    768
#define DF    3072
#define QKVN  2304
#define LSEQ  64
#define BH    448
#define NHEAD 12
#define OUTSZ 22020096

__device__ float  g_u[MROWS * DM];
__device__ __half g_uh[MROWS * DM];
__device__ __half g_qkvh[MROWS * QKVN];
__device__ __half g_oh[MROWS * DM];
__device__ float  g_t[MROWS * DM];
__device__ __half g_ffh[MROWS * DF];
__device__ float  g_scores[BH * NHEAD * LSEQ * LSEQ];
__device__ float  g_stats[2 * DM];
__device__ __half g_wqkvt[3 * QKVN * DM];
__device__ float  g_bqkv[3 * QKVN];
__device__ __half g_wot[3 * DM * DM];
__device__ __half g_w1t[3 * DM * DF];
__device__ __half g_w2t[3 * DF * DM];

__device__ __forceinline__ uint32_t pack_half2(float lo, float hi) {
    uint32_t r;
    asm("cvt.rn.f16x2.f32 %0, %1, %2;" : "=r"(r) : "f"(hi), "f"(lo));
    return r;
}

// ---------------------------------------------------------------------------
// fp16 MMA GEMM: BM=BN=128, BK=64, 8 warps (2m x 4n), warp tile 64x32,
// m16n8k16, ldmatrix, 3-stage cp.async, ONE sync per iter.
// smem 110592 B/CTA -> 2 CTAs/SM. RESID: residual + atomic BN stats.
// ---------------------------------------------------------------------------
#define HROW 72
#define HSTAGE (128 * HROW * 2)            // 18432 B per matrix per stage
#define HG_SMEM (3 * 2 * HSTAGE)           // 110592 B

__device__ __forceinline__ void cpasync16u(uint32_t sa, const void* gp) {
    asm volatile("cp.async.cg.shared.global [%0], [%1], 16;" :: "r"(sa), "l"(gp));
}

template<int GELU_EPI, int WRITE_F, int WRITE_H, int RESID>
__global__ __launch_bounds__(256, 2) void hgemm(
    const __half* __restrict__ A, const __half* __restrict__ Bt,
    const float* __restrict__ bias, float* __restrict__ Cf,
    __half* __restrict__ Ch, float* __restrict__ U, float* __restrict__ stats,
    int N, int K)
{
    extern __shared__ char dsm[];
    const uint32_t sbase = (uint32_t)__cvta_generic_to_shared(dsm);
    const int tid  = threadIdx.x;
    const int wid  = tid >> 5, lane = tid & 31;
    const int g    = lane >> 2, tig = lane & 3;
    const int wm   = (wid & 1) * 64;
    const int wn   = (wid >> 1) * 32;
    const int m0   = blockIdx.y * 128, n0 = blockIdx.x * 128;
    const int NK   = K >> 6;

    const int arow  = lane & 15;
    const int akoff = (lane & 16) >> 1;
    const int nrow  = ((lane & 16) >> 1) + (lane & 7);
    const int bkoff = lane & 8;
    const uint32_t aOff = sbase + ((wm + arow) * HROW + akoff) * 2;
    const uint32_t bOff = sbase + HSTAGE + ((wn + nrow) * HROW + bkoff) * 2;

    float acc[16][4];
#pragma unroll
    for (int i = 0; i < 16; i++)
#pragma unroll
        for (int j = 0; j < 4; j++) acc[i][j] = 0.f;

    // stage load: A,B each 128 rows x 64 halfs = 1024 16B-chunks -> 4/thread each
    auto load_stage = [&](int stg, int it) {
        const __half* Ab = A + (size_t)m0 * K + it * 64;
        const __half* Bb = Bt + (size_t)n0 * K + it * 64;
        uint32_t dA = sbase + stg * (2 * HSTAGE);
        uint32_t dB = dA + HSTAGE;
#pragma unroll
        for (int r = 0; r < 4; r++) {
            int c = tid + 256 * r;
            int row = c >> 3, cj = c & 7;
            cpasync16u(dA + (row * HROW + cj * 8) * 2, Ab + (size_t)row * K + cj * 8);
            cpasync16u(dB + (row * HROW + cj * 8) * 2, Bb + (size_t)row * K + cj * 8);
        }
        asm volatile("cp.async.commit_group;");
    };

    load_stage(0, 0);
    if (NK > 1) load_stage(1, 1);

    for (int it = 0; it < NK; it++) {
        const int s = it % 3;
        if (it + 1 < NK) asm volatile("cp.async.wait_group 1;");
        else             asm volatile("cp.async.wait_group 0;");
        __syncthreads();
        if (it + 2 < NK) load_stage((it + 2) % 3, it + 2);

        const uint32_t aS = aOff + s * (2 * HSTAGE);
        const uint32_t bS = bOff + s * (2 * HSTAGE);
#pragma unroll
        for (int ks = 0; ks < 4; ks++) {
            uint32_t a[4][4], b[4][2];
#pragma unroll
            for (int mt = 0; mt < 4; mt++) {
                uint32_t ad = aS + mt * (16 * HROW * 2) + ks * 32;
                asm volatile("ldmatrix.sync.aligned.m8n8.x4.shared.b16 {%0,%1,%2,%3}, [%4];"
                             : "=r"(a[mt][0]), "=r"(a[mt][1]), "=r"(a[mt][2]), "=r"(a[mt][3])
                             : "r"(ad));
            }
#pragma unroll
            for (int p = 0; p < 2; p++) {
                uint32_t bd = bS + p * (16 * HROW * 2) + ks * 32;
                asm volatile("ldmatrix.sync.aligned.m8n8.x4.shared.b16 {%0,%1,%2,%3}, [%4];"
                             : "=r"(b[2 * p][0]), "=r"(b[2 * p][1]),
                               "=r"(b[2 * p + 1][0]), "=r"(b[2 * p + 1][1])
                             : "r"(bd));
            }
#pragma unroll
            for (int mt = 0; mt < 4; mt++)
#pragma unroll
                for (int nt = 0; nt < 4; nt++) {
                    float* c = acc[mt * 4 + nt];
                    asm volatile(
                        "mma.sync.aligned.m16n8k16.row.col.f32.f16.f16.f32 "
                        "{%0,%1,%2,%3}, {%4,%5,%6,%7}, {%8,%9}, {%0,%1,%2,%3};"
                        : "+f"(c[0]), "+f"(c[1]), "+f"(c[2]), "+f"(c[3])
                        : "r"(a[mt][0]), "r"(a[mt][1]), "r"(a[mt][2]), "r"(a[mt][3]),
                          "r"(b[nt][0]), "r"(b[nt][1]));
                }
        }
    }

    float cs[8], cq[8];
    if (RESID) {
#pragma unroll
        for (int i = 0; i < 8; i++) { cs[i] = 0.f; cq[i] = 0.f; }
    }
#pragma unroll
    for (int mt = 0; mt < 4; mt++) {
#pragma unroll
        for (int nt = 0; nt < 4; nt++) {
            const float* c = acc[mt * 4 + nt];
            int col = n0 + wn + nt * 8 + 2 * tig;
            float b0 = bias[col], b1 = bias[col + 1];
            int r0 = m0 + wm + mt * 16 + g;
            float2 v0, v1;
            v0.x = c[0] + b0; v0.y = c[1] + b1;
            v1.x = c[2] + b0; v1.y = c[3] + b1;
            if (GELU_EPI) {
                v0.x = 0.5f * v0.x * (1.0f + erff(v0.x * 0.70710678118654752f));
                v0.y = 0.5f * v0.y * (1.0f + erff(v0.y * 0.70710678118654752f));
                v1.x = 0.5f * v1.x * (1.0f + erff(v1.x * 0.70710678118654752f));
                v1.y = 0.5f * v1.y * (1.0f + erff(v1.y * 0.70710678118654752f));
            }
            if (RESID) {
                float2 u0 = *(float2*)&U[(size_t)r0 * N + col];
                float2 u1 = *(float2*)&U[(size_t)(r0 + 8) * N + col];
                v0.x += u0.x; v0.y += u0.y;
                v1.x += u1.x; v1.y += u1.y;
                *(float2*)&U[(size_t)r0 * N + col] = v0;
                *(float2*)&U[(size_t)(r0 + 8) * N + col] = v1;
                cs[nt * 2 + 0] += v0.x + v1.x;
                cs[nt * 2 + 1] += v0.y + v1.y;
                cq[nt * 2 + 0] += v0.x * v0.x + v1.x * v1.x;
                cq[nt * 2 + 1] += v0.y * v0.y + v1.y * v1.y;
            }
            if (WRITE_F) {
                *(float2*)&Cf[(size_t)r0 * N + col] = v0;
                *(float2*)&Cf[(size_t)(r0 + 8) * N + col] = v1;
            }
            if (WRITE_H) {
                __half2 h0, h1;
                h0.x = __float2half(v0.x); h0.y = __float2half(v0.y);
                h1.x = __float2half(v1.x); h1.y = __float2half(v1.y);
                *(__half2*)&Ch[(size_t)r0 * N + col] = h0;
                *(__half2*)&Ch[(size_t)(r0 + 8) * N + col] = h1;
            }
        }
    }
    if (RESID) {
#pragma unroll
        for (int i = 0; i < 8; i++) {
            cs[i] += __shfl_down_sync(0xffffffffu, cs[i], 16);
            cs[i] += __shfl_down_sync(0xffffffffu, cs[i], 8);
            cs[i] += __shfl_down_sync(0xffffffffu, cs[i], 4);
            cq[i] += __shfl_down_sync(0xffffffffu, cq[i], 16);
            cq[i] += __shfl_down_sync(0xffffffffu, cq[i], 8);
            cq[i] += __shfl_down_sync(0xffffffffu, cq[i], 4);
        }
        if (lane < 4) {
#pragma unroll
            for (int nt = 0; nt < 4; nt++) {
                int col = n0 + wn + nt * 8 + 2 * tig;
                atomicAdd(&stats[col],     cs[nt * 2 + 0]);
                atomicAdd(&stats[col + 1], cs[nt * 2 + 1]);
                atomicAdd(&stats[DM + col],     cq[nt * 2 + 0]);
                atomicAdd(&stats[DM + col + 1], cq[nt * 2 + 1]);
            }
        }
    }
}

// ---------------------------------------------------------------------------
// fp32 SGEMM (patch embed, K=16)
// ---------------------------------------------------------------------------
__global__ __launch_bounds__(256, 2) void gemm_kernel(
    const float* __restrict__ A, const float* __restrict__ B,
    const float* __restrict__ bias, float* __restrict__ C,
    int Mdim, int Ndim, int Kdim)
{
    __shared__ float As[16][128];
    __shared__ float Bs[16][132];
    const int tid = threadIdx.x;
    const int tx = tid & 15, ty = tid >> 4;
    const int m0 = blockIdx.y * 128, n0 = blockIdx.x * 128;
    float acc[8][8];
#pragma unroll
    for (int i = 0; i < 8; i++)
#pragma unroll
        for (int j = 0; j < 8; j++) acc[i][j] = 0.f;
    for (int k0 = 0; k0 < Kdim; k0 += 16) {
#pragma unroll
        for (int s = 0; s < 2; s++) {
            int f4 = tid + 256 * s;
            int row = f4 >> 2, kq = (f4 & 3) * 4;
            float4 av = *(const float4*)&A[(size_t)(m0 + row) * Kdim + k0 + kq];
            As[kq + 0][row] = av.x; As[kq + 1][row] = av.y;
            As[kq + 2][row] = av.z; As[kq + 3][row] = av.w;
        }
#pragma unroll
        for (int s = 0; s < 2; s++) {
            int f4 = tid + 256 * s;
            int row = f4 >> 5, nq = (f4 & 31) * 4;
            *(float4*)&Bs[row][nq] = *(const float4*)&B[(size_t)(k0 + row) * Ndim + n0 + nq];
        }
        __syncthreads();
#pragma unroll
        for (int k = 0; k < 16; k++) {
            float a[8], b[8];
            *(float4*)&a[0] = *(const float4*)&As[k][ty * 8];
            *(float4*)&a[4] = *(const float4*)&As[k][ty * 8 + 4];
            *(float4*)&b[0] = *(const float4*)&Bs[k][tx * 8];
            *(float4*)&b[4] = *(const float4*)&Bs[k][tx * 8 + 4];
#pragma unroll
            for (int i = 0; i < 8; i++)
#pragma unroll
                for (int j = 0; j < 8; j++) acc[i][j] += a[i] * b[j];
        }
        __syncthreads();
    }
#pragma unroll
    for (int i = 0; i < 8; i++) {
        int row = m0 + ty * 8 + i;
#pragma unroll
        for (int j = 0; j < 8; j++) {
            int col = n0 + tx * 8 + j;
            C[(size_t)row * Ndim + col] = acc[i][j] + bias[col];
        }
    }
}

// ---------------------------------------------------------------------------
// QKV weight transpose + bias concat
// ---------------------------------------------------------------------------
__global__ void qkv_wtrans_kernel(
    const float* __restrict__ Wq, const float* __restrict__ Wk,
    const float* __restrict__ Wv, const float* __restrict__ bq,
    const float* __restrict__ bk, const float* __restrict__ bv,
    __half* __restrict__ wout, float* __restrict__ bout)
{
    int z = blockIdx.z;
    if (z == 3) {
        int idx = (blockIdx.y * gridDim.x + blockIdx.x) * 256 +
                  threadIdx.y * 32 + threadIdx.x;
        if (idx < QKVN) {
            int sec = idx / DM, cc = idx % DM;
            const float* src = (sec == 0) ? bq : (sec == 1) ? bk : bv;
            bout[idx] = src[cc];
        }
        return;
    }
    const float* W = (z == 0) ? Wq : (z == 1) ? Wk : Wv;
    __shared__ float tl[32][33];
    int c0 = blockIdx.x * 32, r0 = blockIdx.y * 32;
#pragma unroll
    for (int i = 0; i < 32; i += 8)
        tl[threadIdx.y + i][threadIdx.x] = W[(size_t)(r0 + threadIdx.y + i) * DM + c0 + threadIdx.x];
    __syncthreads();
#pragma unroll
    for (int i = 0; i < 32; i += 8)
        wout[(size_t)(z * DM + c0 + threadIdx.y + i) * DM + r0 + threadIdx.x] =
            __float2half(tl[threadIdx.x][threadIdx.y + i]);
}

__global__ void wtrans_kernel(const float* __restrict__ in, __half* __restrict__ out,
                              int R, int Ccols)
{
    __shared__ float tl[32][33];
    int c0 = blockIdx.x * 32, r0 = blockIdx.y * 32;
#pragma unroll
    for (int i = 0; i < 32; i += 8)
        tl[threadIdx.y + i][threadIdx.x] = in[(size_t)(r0 + threadIdx.y + i) * Ccols + c0 + threadIdx.x];
    __syncthreads();
#pragma unroll
    for (int i = 0; i < 32; i += 8)
        out[(size_t)(c0 + threadIdx.y + i) * R + r0 + threadIdx.x] =
            __float2half(tl[threadIdx.x][threadIdx.y + i]);
}

// ---------------------------------------------------------------------------
// Tensor-core attention per (batch, head) (as R12, passing).
// ---------------------------------------------------------------------------
#define AROW 72

__global__ __launch_bounds__(128) void attn_mma_kernel(
    const __half* __restrict__ QKV, float* __restrict__ scores,
    __half* __restrict__ O, float* __restrict__ attn_out, int has_prev)
{
    __shared__ __align__(16) __half Qs[64 * AROW];
    __shared__ __align__(16) __half Ks[64 * AROW];
    __shared__ __align__(16) __half Vs[64 * AROW];

    const int bh = blockIdx.x;
    const int bv = bh / NHEAD, h = bh % NHEAD;
    const int row0 = bv * LSEQ, c0 = h * 64;
    const int tid = threadIdx.x;
    const int wid = tid >> 5, lane = tid & 31;
    const int g = lane >> 2, tig = lane & 3;
    const int wm = wid * 16;
    const size_t sb = (size_t)bh * 4096;

    for (int e = tid; e < 512; e += 128) {
        int r = e >> 3, cj = e & 7;
        const __half* base = QKV + (size_t)(row0 + r) * QKVN + c0 + cj * 8;
        *(uint4*)&Qs[r * AROW + cj * 8] = *(const uint4*)(base);
        *(uint4*)&Ks[r * AROW + cj * 8] = *(const uint4*)(base + DM);
        *(uint4*)&Vs[r * AROW + cj * 8] = *(const uint4*)(base + 2 * DM);
    }
    __syncthreads();

    const uint32_t qsb = (uint32_t)__cvta_generic_to_shared(Qs);
    const uint32_t ksb = (uint32_t)__cvta_generic_to_shared(Ks);
    const uint32_t vsb = (uint32_t)__cvta_generic_to_shared(Vs);

    const int arow  = lane & 15;
    const int akoff = (lane & 16) >> 1;
    const int nrow  = ((lane & 16) >> 1) + (lane & 7);
    const int bkoff = lane & 8;

    float sc[8][4];
#pragma unroll
    for (int i = 0; i < 8; i++)
#pragma unroll
        for (int j = 0; j < 4; j++) sc[i][j] = 0.f;

#pragma unroll
    for (int ks = 0; ks < 4; ks++) {
        uint32_t a[4];
        uint32_t ad = qsb + ((wm + arow) * AROW + 16 * ks + akoff) * 2;
        asm volatile("ldmatrix.sync.aligned.m8n8.x4.shared.b16 {%0,%1,%2,%3}, [%4];"
                     : "=r"(a[0]), "=r"(a[1]), "=r"(a[2]), "=r"(a[3]) : "r"(ad));
#pragma unroll
        for (int p = 0; p < 4; p++) {
            uint32_t b[4];
            uint32_t bd = ksb + ((16 * p + nrow) * AROW + 16 * ks + bkoff) * 2;
            asm volatile("ldmatrix.sync.aligned.m8n8.x4.shared.b16 {%0,%1,%2,%3}, [%4];"
                         : "=r"(b[0]), "=r"(b[1]), "=r"(b[2]), "=r"(b[3]) : "r"(bd));
#pragma unroll
            for (int q = 0; q < 2; q++) {
                float* c = sc[2 * p + q];
                asm volatile(
                    "mma.sync.aligned.m16n8k16.row.col.f32.f16.f16.f32 "
                    "{%0,%1,%2,%3}, {%4,%5,%6,%7}, {%8,%9}, {%0,%1,%2,%3};"
                    : "+f"(c[0]), "+f"(c[1]), "+f"(c[2]), "+f"(c[3])
                    : "r"(a[0]), "r"(a[1]), "r"(a[2]), "r"(a[3]),
                      "r"(b[2 * q]), "r"(b[2 * q + 1]));
            }
        }
    }

    const int ri0 = wm + g, ri1 = wm + g + 8;
    float m0 = -1e30f, m1 = -1e30f;
#pragma unroll
    for (int nt = 0; nt < 8; nt++) {
        float v0 = sc[nt][0] * 0.125f, v1 = sc[nt][1] * 0.125f;
        float v2 = sc[nt][2] * 0.125f, v3 = sc[nt][3] * 0.125f;
        int coff = 8 * nt + 2 * tig;
        if (has_prev) {
            float2 p0 = *(float2*)&scores[sb + ri0 * 64 + coff];
            float2 p1 = *(float2*)&scores[sb + ri1 * 64 + coff];
            v0 += p0.x; v1 += p0.y; v2 += p1.x; v3 += p1.y;
        }
        float2 s0 = { v0, v1 }, s1 = { v2, v3 };
        *(float2*)&scores[sb + ri0 * 64 + coff] = s0;
        *(float2*)&scores[sb + ri1 * 64 + coff] = s1;
        sc[nt][0] = v0; sc[nt][1] = v1; sc[nt][2] = v2; sc[nt][3] = v3;
        m0 = fmaxf(m0, fmaxf(v0, v1));
        m1 = fmaxf(m1, fmaxf(v2, v3));
    }
    m0 = fmaxf(m0, __shfl_xor_sync(0xffffffffu, m0, 1));
    m0 = fmaxf(m0, __shfl_xor_sync(0xffffffffu, m0, 2));
    m1 = fmaxf(m1, __shfl_xor_sync(0xffffffffu, m1, 1));
    m1 = fmaxf(m1, __shfl_xor_sync(0xffffffffu, m1, 2));

    float s0 = 0.f, s1 = 0.f;
#pragma unroll
    for (int nt = 0; nt < 8; nt++) {
        sc[nt][0] = __expf(sc[nt][0] - m0);
        sc[nt][1] = __expf(sc[nt][1] - m0);
        sc[nt][2] = __expf(sc[nt][2] - m1);
        sc[nt][3] = __expf(sc[nt][3] - m1);
        s0 += sc[nt][0] + sc[nt][1];
        s1 += sc[nt][2] + sc[nt][3];
    }
    s0 += __shfl_xor_sync(0xffffffffu, s0, 1);
    s0 += __shfl_xor_sync(0xffffffffu, s0, 2);
    s1 += __shfl_xor_sync(0xffffffffu, s1, 1);
    s1 += __shfl_xor_sync(0xffffffffu, s1, 2);
    float inv0 = 1.0f / s0, inv1 = 1.0f / s1;

#pragma unroll
    for (int nt = 0; nt < 8; nt++) {
        sc[nt][0] *= inv0; sc[nt][1] *= inv0;
        sc[nt][2] *= inv1; sc[nt][3] *= inv1;
        if (attn_out) {
            int coff = 8 * nt + 2 * tig;
            float2 p0 = { sc[nt][0], sc[nt][1] };
            float2 p1 = { sc[nt][2], sc[nt][3] };
            *(float2*)&attn_out[sb + ri0 * 64 + coff] = p0;
            *(float2*)&attn_out[sb + ri1 * 64 + coff] = p1;
        }
    }

    float oacc[8][4];
#pragma unroll
    for (int i = 0; i < 8; i++)
#pragma unroll
        for (int j = 0; j < 4; j++) oacc[i][j] = 0.f;

    const int vrow = (lane & 7) + (lane & 8);
    const int vkoff = (lane & 16) >> 1;
#pragma unroll
    for (int jt = 0; jt < 4; jt++) {
        uint32_t a[4];
        a[0] = pack_half2(sc[2 * jt][0], sc[2 * jt][1]);
        a[1] = pack_half2(sc[2 * jt][2], sc[2 * jt][3]);
        a[2] = pack_half2(sc[2 * jt + 1][0], sc[2 * jt + 1][1]);
        a[3] = pack_half2(sc[2 * jt + 1][2], sc[2 * jt + 1][3]);
#pragma unroll
        for (int dp = 0; dp < 4; dp++) {
            uint32_t b[4];
            uint32_t bd = vsb + ((16 * jt + vrow) * AROW + 16 * dp + vkoff) * 2;
            asm volatile("ldmatrix.sync.aligned.m8n8.x4.trans.shared.b16 {%0,%1,%2,%3}, [%4];"
                         : "=r"(b[0]), "=r"(b[1]), "=r"(b[2]), "=r"(b[3]) : "r"(bd));
#pragma unroll
            for (int q = 0; q < 2; q++) {
                float* c = oacc[2 * dp + q];
                asm volatile(
                    "mma.sync.aligned.m16n8k16.row.col.f32.f16.f16.f32 "
                    "{%0,%1,%2,%3}, {%4,%5,%6,%7}, {%8,%9}, {%0,%1,%2,%3};"
                    : "+f"(c[0]), "+f"(c[1]), "+f"(c[2]), "+f"(c[3])
                    : "r"(a[0]), "r"(a[1]), "r"(a[2]), "r"(a[3]),
                      "r"(b[2 * q]), "r"(b[2 * q + 1]));
            }
        }
    }

#pragma unroll
    for (int nt = 0; nt < 8; nt++) {
        int col = c0 + 8 * nt + 2 * tig;
        __half2 h0, h1;
        h0.x = __float2half(oacc[nt][0]); h0.y = __float2half(oacc[nt][1]);
        h1.x = __float2half(oacc[nt][2]); h1.y = __float2half(oacc[nt][3]);
        *(__half2*)&O[(size_t)(row0 + ri0) * DM + col] = h0;
        *(__half2*)&O[(size_t)(row0 + ri1) * DM + col] = h1;
    }
}

// ---------------------------------------------------------------------------
// BatchNorm finalize
// ---------------------------------------------------------------------------
__global__ void zero_stats_kernel(float* stats)
{
    int idx = blockIdx.x * 256 + threadIdx.x;
    if (idx < 2 * DM) stats[idx] = 0.f;
}

__global__ __launch_bounds__(256) void bn_norm_kernel(
    float* __restrict__ u, __half* __restrict__ uh, const float* __restrict__ stats,
    const float* __restrict__ g, const float* __restrict__ be)
{
    int idx = blockIdx.x * 256 + threadIdx.x;
    int c = idx % DM;
    const float invM = 1.0f / (float)MROWS;
    float mean = stats[c] * invM;
    float var = stats[DM + c] * invM - mean * mean;
    float iv = rsqrtf(var + 1e-5f);
    float val = (u[idx] - mean) * iv * g[c] + be[c];
    u[idx] = val;
    uh[idx] = __float2half(val);
}

// ---------------------------------------------------------------------------
// Misc remap / transposes
// ---------------------------------------------------------------------------
__global__ __launch_bounds__(256) void remap_embed_kernel(
    const float* __restrict__ h, const float* __restrict__ Wpos,
    float* __restrict__ u, __half* __restrict__ uh)
{
    int idx = blockIdx.x * 256 + threadIdx.x;
    int ru = idx / DM, d = idx % DM;
    int bv = ru >> 6, n = ru & 63;
    int b = bv / 7, v = bv % 7;
    int rh = (b * 64 + n) * 7 + v;
    float val = h[(size_t)rh * DM + d] + Wpos[n * DM + d];
    u[idx] = val;
    uh[idx] = __float2half(val);
}

__global__ void transpose_h_kernel(const float* __restrict__ h, float* __restrict__ out)
{
    __shared__ float tile[32][33];
    int bv = blockIdx.z, b = bv / 7, v = bv % 7;
    int d0 = blockIdx.x * 32, n0 = blockIdx.y * 32;
#pragma unroll
    for (int i = 0; i < 32; i += 8) {
        int n = n0 + threadIdx.y + i;
        int d = d0 + threadIdx.x;
        tile[threadIdx.y + i][threadIdx.x] = h[((size_t)(b * 64 + n) * 7 + v) * DM + d];
    }
    __syncthreads();
#pragma unroll
    for (int i = 0; i < 32; i += 8) {
        int d = d0 + threadIdx.y + i;
        int n = n0 + threadIdx.x;
        out[((size_t)bv * DM + d) * LSEQ + n] = tile[threadIdx.x][threadIdx.y + i];
    }
}

__global__ void transpose_z_bn_kernel(
    const float* __restrict__ u, const float* __restrict__ stats,
    const float* __restrict__ g, const float* __restrict__ be,
    float* __restrict__ out)
{
    __shared__ float tile[32][33];
    int bv = blockIdx.z;
    int d0 = blockIdx.x * 32, n0 = blockIdx.y * 32;
    int d = d0 + threadIdx.x;
    const float invM = 1.0f / (float)MROWS;
    float mean = stats[d] * invM;
    float var = stats[DM + d] * invM - mean * mean;
    float scl = rsqrtf(var + 1e-5f) * g[d];
    float off = be[d] - mean * scl;
#pragma unroll
    for (int i = 0; i < 32; i += 8) {
        int n = n0 + threadIdx.y + i;
        tile[threadIdx.y + i][threadIdx.x] =
            u[(size_t)(bv * 64 + n) * DM + d] * scl + off;
    }
    __syncthreads();
#pragma unroll
    for (int i = 0; i < 32; i += 8) {
        int dd = d0 + threadIdx.y + i;
        int n = n0 + threadIdx.x;
        out[((size_t)bv * DM + dd) * LSEQ + n] = tile[threadIdx.x][threadIdx.y + i];
    }
}

// ---------------------------------------------------------------------------

extern "C" void kernel_launch(void* const* d_in, const int* in_sizes, int n_in,
                              void* d_out, int out_size)
{
    const float* x    = (const float*)d_in[0];
    const float* Wp   = (const float*)d_in[1];
    const float* bp   = (const float*)d_in[2];
    const float* Wpos = (const float*)d_in[3];
    const float* Wq   = (const float*)d_in[4];
    const float* bq   = (const float*)d_in[5];
    const float* Wk   = (const float*)d_in[6];
    const float* bk   = (const float*)d_in[7];
    const float* Wv   = (const float*)d_in[8];
    const float* bv_  = (const float*)d_in[9];
    const float* Wo   = (const float*)d_in[10];
    const float* bo   = (const float*)d_in[11];
    const float* g1   = (const float*)d_in[12];
    const float* be1  = (const float*)d_in[13];
    const float* W1   = (const float*)d_in[14];
    const float* b1   = (const float*)d_in[15];
    const float* W2   = (const float*)d_in[16];
    const float* b2   = (const float*)d_in[17];
    const float* g2   = (const float*)d_in[18];
    const float* be2  = (const float*)d_in[19];

    float* out      = (float*)d_out;
    float* out_z    = out;
    float* out_h    = out + OUTSZ;
    float* out_attn = out + 2 * (size_t)OUTSZ;

    float *u, *t, *sc, *st, *bqkv;
    __half *uh, *qkvh, *oh, *ffh, *wqkvt, *wot, *w1t, *w2t;
    cudaGetSymbolAddress((void**)&u,  g_u);
    cudaGetSymbolAddress((void**)&uh, g_uh);
    cudaGetSymbolAddress((void**)&qkvh, g_qkvh);
    cudaGetSymbolAddress((void**)&oh, g_oh);
    cudaGetSymbolAddress((void**)&t,  g_t);
    cudaGetSymbolAddress((void**)&ffh, g_ffh);
    cudaGetSymbolAddress((void**)&sc, g_scores);
    cudaGetSymbolAddress((void**)&st, g_stats);
    cudaGetSymbolAddress((void**)&bqkv, g_bqkv);
    cudaGetSymbolAddress((void**)&wqkvt, g_wqkvt);
    cudaGetSymbolAddress((void**)&wot, g_wot);
    cudaGetSymbolAddress((void**)&w1t, g_w1t);
    cudaGetSymbolAddress((void**)&w2t, g_w2t);

    cudaFuncSetAttribute(hgemm<0, 0, 1, 0>, cudaFuncAttributeMaxDynamicSharedMemorySize, HG_SMEM);
    cudaFuncSetAttribute(hgemm<0, 0, 0, 1>, cudaFuncAttributeMaxDynamicSharedMemorySize, HG_SMEM);
    cudaFuncSetAttribute(hgemm<1, 0, 1, 0>, cudaFuncAttributeMaxDynamicSharedMemorySize, HG_SMEM);

    const dim3 blk(256);
    const int elemBlocks = (MROWS * DM) / 256;
    const dim3 tgrid(24, 2, BH);
    const dim3 tblk32(32, 8);
    const dim3 gQKV(QKVN / 128, MROWS / 128);
    const dim3 gD(DM / 128, MROWS / 128);
    const dim3 gF(DF / 128, MROWS / 128);
    const dim3 gqkvW(24, 24, 4);
    const dim3 gdd(DM / 32, DM / 32);
    const dim3 g1d(DF / 32, DM / 32);
    const dim3 g2d(DM / 32, DF / 32);

    qkv_wtrans_kernel<<<gqkvW, tblk32>>>(Wq, Wk, Wv, bq, bk, bv_, wqkvt, bqkv);   // 0
    gemm_kernel<<<dim3(DM / 128, MROWS / 128), blk>>>(x, Wp, bp, t, MROWS, DM, 16); // 1
    remap_embed_kernel<<<elemBlocks, blk>>>(t, Wpos, u, uh);                       // 2
    hgemm<0, 0, 1, 0><<<gQKV, blk, HG_SMEM>>>(uh, wqkvt, bqkv,
                                              nullptr, qkvh, nullptr, nullptr, QKVN, DM); // 3

    transpose_h_kernel<<<tgrid, tblk32>>>(t, out_h);
    for (int l = 1; l < 3; l++)
        qkv_wtrans_kernel<<<gqkvW, tblk32>>>(
            Wq + (size_t)l * DM * DM, Wk + (size_t)l * DM * DM, Wv + (size_t)l * DM * DM,
            bq + l * DM, bk + l * DM, bv_ + l * DM,
            wqkvt + (size_t)l * QKVN * DM, bqkv + l * QKVN);
    for (int l = 0; l < 3; l++) {
        wtrans_kernel<<<gdd, tblk32>>>(Wo + (size_t)l * DM * DM, wot + (size_t)l * DM * DM, DM, DM);
        wtrans_kernel<<<g1d, tblk32>>>(W1 + (size_t)l * DM * DF, w1t + (size_t)l * DM * DF, DM, DF);
        wtrans_kernel<<<g2d, tblk32>>>(W2 + (size_t)l * DF * DM, w2t + (size_t)l * DF * DM, DF, DM);
    }

    for (int l = 0; l < 3; l++) {
        if (l > 0)
            hgemm<0, 0, 1, 0><<<gQKV, blk, HG_SMEM>>>(
                uh, wqkvt + (size_t)l * QKVN * DM, bqkv + l * QKVN,
                nullptr, qkvh, nullptr, nullptr, QKVN, DM);

        attn_mma_kernel<<<BH * NHEAD, 128>>>(
            qkvh, sc, oh, (l == 2) ? out_attn : nullptr, (l > 0) ? 1 : 0);

        zero_stats_kernel<<<6, 256>>>(st);
        hgemm<0, 0, 0, 1><<<gD, blk, HG_SMEM>>>(oh, wot + (size_t)l * DM * DM, bo + l * DM,
                                                nullptr, nullptr, u, st, DM, DM);
        bn_norm_kernel<<<elemBlocks, blk>>>(u, uh, st, g1 + l * DM, be1 + l * DM);

        hgemm<1, 0, 1, 0><<<gF, blk, HG_SMEM>>>(uh, w1t + (size_t)l * DM * DF, b1 + l * DF,
                                                nullptr, ffh, nullptr, nullptr, DF, DM);
        zero_stats_kernel<<<6, 256>>>(st);
        hgemm<0, 0, 0, 1><<<gD, blk, HG_SMEM>>>(ffh, w2t + (size_t)l * DF * DM, b2 + l * DM,
                                                nullptr, nullptr, u, st, DM, DF);
        if (l < 2)
            bn_norm_kernel<<<elemBlocks, blk>>>(u, uh, st, g2 + l * DM, be2 + l * DM);
    }

    transpose_z_bn_kernel<<<tgrid, tblk32>>>(u, st, g2 + 2 * DM, be2 + 2 * DM, out_z);
}